// round 1
// baseline (speedup 1.0000x reference)
#include <cuda_runtime.h>

#define D        128
#define N_INIT   100000
#define LVLS     64
#define M        4096
#define N_RULES  256
#define N_TOT    (N_INIT + LVLS * M)

#define EVAL_BLOCKS 1024

// level kernel shared memory layout (bytes)
#define SM_W_BYTES   131072               // 256 x 128 fp32 weights (as f32x2 pairs)
#define SM_PE_BYTES  32768                // 16 nodes x 256 dup-f32x2
#define SM_B_BYTES   512                  // bias 128 fp32
#define SM_META_BYTES 192                 // j[16], p0[16], p1[16]
#define LEVEL_SMEM   (SM_W_BYTES + SM_PE_BYTES + SM_B_BYTES + SM_META_BYTES)

__device__ float g_store[(size_t)N_TOT * D];     // node embeddings
__device__ int   g_order[LVLS * M];              // node ids grouped by rule
__device__ int   g_ruleoff[LVLS * (N_RULES + 1)];
__device__ float g_partial[EVAL_BLOCKS * 6];     // A, B, posOK, negOK, sum_pos, sum_neg

// ---------------------------------------------------------------------------
// K1: init embeddings  store[i] = thax_table[init_thax[i]] + sine_table[init_sine[i]]
// ---------------------------------------------------------------------------
__global__ void init_embed_kernel(const float4* __restrict__ thax,
                                  const float4* __restrict__ sine,
                                  const int* __restrict__ it,
                                  const int* __restrict__ is)
{
    int tid = blockIdx.x * blockDim.x + threadIdx.x;
    int total = N_INIT * (D / 4);
    float4* st = (float4*)g_store;
    for (int k = tid; k < total; k += gridDim.x * blockDim.x) {
        int i = k >> 5;        // D/4 = 32 chunks per node
        int c = k & 31;
        float4 a = thax[(size_t)it[i] * 32 + c];
        float4 b = sine[(size_t)is[i] * 32 + c];
        st[(size_t)i * 32 + c] = make_float4(a.x + b.x, a.y + b.y, a.z + b.z, a.w + b.w);
    }
}

// ---------------------------------------------------------------------------
// K2: group nodes by rule (counting sort), one block per level
// ---------------------------------------------------------------------------
__global__ void group_kernel(const int* __restrict__ rules)
{
    int lvl = blockIdx.x;
    __shared__ int counts[N_RULES];
    __shared__ int offs[N_RULES + 1];
    __shared__ int cursor[N_RULES];

    for (int r = threadIdx.x; r < N_RULES; r += blockDim.x) counts[r] = 0;
    __syncthreads();
    for (int j = threadIdx.x; j < M; j += blockDim.x)
        atomicAdd(&counts[rules[lvl * M + j]], 1);
    __syncthreads();
    if (threadIdx.x == 0) {
        int s = 0;
        for (int r = 0; r < N_RULES; r++) { offs[r] = s; s += counts[r]; }
        offs[N_RULES] = s;
    }
    __syncthreads();
    for (int r = threadIdx.x; r < N_RULES; r += blockDim.x) cursor[r] = offs[r];
    for (int r = threadIdx.x; r <= N_RULES; r += blockDim.x)
        g_ruleoff[lvl * (N_RULES + 1) + r] = offs[r];
    __syncthreads();
    for (int j = threadIdx.x; j < M; j += blockDim.x) {
        int r = rules[lvl * M + j];
        int p = atomicAdd(&cursor[r], 1);
        g_order[lvl * M + p] = j;   // order within a rule is arbitrary; per-node math is independent
    }
}

// ---------------------------------------------------------------------------
// K3: one level. One CTA per rule. W[rule] staged in smem (128 KB).
// 256 threads: o2 = tid&63 (output pair 2*o2, 2*o2+1), gg = tid>>6 (node group).
// Each thread accumulates 4 nodes (slots gg, gg+4, gg+8, gg+12) with fma.rn.f32x2.
// ---------------------------------------------------------------------------
__global__ void __launch_bounds__(256, 1)
level_kernel(const float* __restrict__ rule_W,
             const float* __restrict__ rule_b,
             const int* __restrict__ parents,
             int lvl)
{
    extern __shared__ unsigned char smem_raw[];
    unsigned long long* Wsh = (unsigned long long*)smem_raw;                   // [256][64] pairs
    unsigned long long* PE  = (unsigned long long*)(smem_raw + SM_W_BYTES);    // [16][256] dup pairs
    float* bsh = (float*)(smem_raw + SM_W_BYTES + SM_PE_BYTES);                // [128]
    int*   meta = (int*)(smem_raw + SM_W_BYTES + SM_PE_BYTES + SM_B_BYTES);    // [48]

    int r = blockIdx.x;
    int start = g_ruleoff[lvl * (N_RULES + 1) + r];
    int end   = g_ruleoff[lvl * (N_RULES + 1) + r + 1];
    if (start == end) return;

    // stage W (vectorized, layout identical: row i = 64 consecutive pairs) + bias
    {
        const float4* Wg  = (const float4*)(rule_W + (size_t)r * 256 * 128);
        float4*       Ws4 = (float4*)Wsh;
        #pragma unroll 4
        for (int k = threadIdx.x; k < 256 * 128 / 4; k += 256) Ws4[k] = Wg[k];
        if (threadIdx.x < 128) bsh[threadIdx.x] = rule_b[r * 128 + threadIdx.x];
    }

    int o2   = threadIdx.x & 63;
    int gg   = threadIdx.x >> 6;
    int half = threadIdx.x >> 7;     // 0 -> parent0 half, 1 -> parent1 half
    int di   = threadIdx.x & 127;

    for (int base = start; base < end; base += 16) {
        __syncthreads();   // previous iteration's compute done (also covers W staging on iter 0)

        if (threadIdx.x < 16) {
            int slot = base + threadIdx.x;
            int j = -1, p0 = 0, p1 = 0;
            if (slot < end) {
                j  = g_order[lvl * M + slot];
                p0 = parents[((size_t)lvl * M + j) * 2 + 0];
                p1 = parents[((size_t)lvl * M + j) * 2 + 1];
            }
            meta[threadIdx.x]      = j;
            meta[16 + threadIdx.x] = p0;
            meta[32 + threadIdx.x] = p1;
        }
        __syncthreads();

        // stage duplicated parent embeddings: PE[s][i] = (pe, pe)
        #pragma unroll 4
        for (int s = 0; s < 16; s++) {
            if (meta[s] >= 0) {
                int p = meta[16 + 16 * half + s];
                float v = g_store[(size_t)p * D + di];
                unsigned int u = __float_as_uint(v);
                PE[s * 256 + threadIdx.x] = ((unsigned long long)u << 32) | u;
            }
        }
        __syncthreads();

        unsigned long long acc0 = 0ull, acc1 = 0ull, acc2 = 0ull, acc3 = 0ull;
        const unsigned long long* pe0 = PE + (gg + 0)  * 256;
        const unsigned long long* pe1 = PE + (gg + 4)  * 256;
        const unsigned long long* pe2 = PE + (gg + 8)  * 256;
        const unsigned long long* pe3 = PE + (gg + 12) * 256;
        const unsigned long long* wp  = Wsh + o2;

        #pragma unroll 8
        for (int i = 0; i < 256; i++) {
            unsigned long long w = wp[(size_t)i * 64];
            asm("fma.rn.f32x2 %0, %1, %2, %0;" : "+l"(acc0) : "l"(pe0[i]), "l"(w));
            asm("fma.rn.f32x2 %0, %1, %2, %0;" : "+l"(acc1) : "l"(pe1[i]), "l"(w));
            asm("fma.rn.f32x2 %0, %1, %2, %0;" : "+l"(acc2) : "l"(pe2[i]), "l"(w));
            asm("fma.rn.f32x2 %0, %1, %2, %0;" : "+l"(acc3) : "l"(pe3[i]), "l"(w));
        }

        float b0 = bsh[2 * o2], b1 = bsh[2 * o2 + 1];
        unsigned long long accs[4] = {acc0, acc1, acc2, acc3};
        #pragma unroll
        for (int t = 0; t < 4; t++) {
            int s = gg + 4 * t;
            int j = meta[s];
            if (j >= 0) {
                float x = __uint_as_float((unsigned int)(accs[t] & 0xffffffffull));
                float y = __uint_as_float((unsigned int)(accs[t] >> 32));
                x = fmaxf(x + b0, 0.0f);
                y = fmaxf(y + b1, 0.0f);
                size_t node = (size_t)N_INIT + (size_t)lvl * M + j;
                ((float2*)(g_store + node * D))[o2] = make_float2(x, y);
            }
        }
    }
}

// ---------------------------------------------------------------------------
// K4: eval + partial reductions (deterministic: fixed grid, fixed slots)
// warp-per-node, lane loads float4, shfl reduce
// ---------------------------------------------------------------------------
__global__ void eval_kernel(const float* __restrict__ eval_w,
                            const float* __restrict__ eval_b,
                            const float* __restrict__ pos_vals,
                            const float* __restrict__ neg_vals)
{
    __shared__ float4 sw[32];
    __shared__ float  wacc[8][6];
    if (threadIdx.x < 32) sw[threadIdx.x] = ((const float4*)eval_w)[threadIdx.x];
    __syncthreads();

    int wid  = threadIdx.x >> 5;
    int lane = threadIdx.x & 31;
    int gw     = blockIdx.x * 8 + wid;
    int nwarps = gridDim.x * 8;
    float eb = eval_b[0];
    float4 w4 = sw[lane];

    float A = 0.f, B = 0.f, pok = 0.f, nok = 0.f, spv = 0.f, snv = 0.f;

    for (size_t node = gw; node < (size_t)N_TOT; node += nwarps) {
        float4 v = ((const float4*)(g_store + node * D))[lane];
        float d = v.x * w4.x + v.y * w4.y + v.z * w4.z + v.w * w4.w;
        #pragma unroll
        for (int off = 16; off; off >>= 1) d += __shfl_down_sync(0xffffffffu, d, off);
        if (lane == 0) {
            float l  = d + eb;
            float pv = pos_vals[node], nv = neg_vals[node];
            float spn = log1pf(expf(-fabsf(l)));        // softplus(-|l|)
            float sp_pos = spn + fmaxf(l, 0.f);         // softplus(l)
            float sp_neg = spn + fmaxf(-l, 0.f);        // softplus(-l)
            A += pv * sp_neg;
            B += nv * sp_pos;
            if (l >= 0.f) pok += pv; else nok += nv;
            spv += pv;
            snv += nv;
        }
    }

    if (lane == 0) {
        wacc[wid][0] = A;   wacc[wid][1] = B;
        wacc[wid][2] = pok; wacc[wid][3] = nok;
        wacc[wid][4] = spv; wacc[wid][5] = snv;
    }
    __syncthreads();
    if (threadIdx.x == 0) {
        float o[6] = {0, 0, 0, 0, 0, 0};
        for (int w = 0; w < 8; w++)
            for (int k = 0; k < 6; k++) o[k] += wacc[w][k];
        for (int k = 0; k < 6; k++) g_partial[blockIdx.x * 6 + k] = o[k];
    }
}

// ---------------------------------------------------------------------------
// K5: final deterministic combine; loss = (sum_neg/sum_pos)*A + B
// ---------------------------------------------------------------------------
__global__ void final_kernel(float* __restrict__ out)
{
    if (blockIdx.x == 0 && threadIdx.x == 0) {
        float A = 0.f, B = 0.f, pok = 0.f, nok = 0.f, spv = 0.f, snv = 0.f;
        for (int b = 0; b < EVAL_BLOCKS; b++) {
            A   += g_partial[b * 6 + 0];
            B   += g_partial[b * 6 + 1];
            pok += g_partial[b * 6 + 2];
            nok += g_partial[b * 6 + 3];
            spv += g_partial[b * 6 + 4];
            snv += g_partial[b * 6 + 5];
        }
        float pw = snv / spv;
        out[0] = pw * A + B;
        out[1] = pok;
        out[2] = nok;
    }
}

// ---------------------------------------------------------------------------
extern "C" void kernel_launch(void* const* d_in, const int* in_sizes, int n_in,
                              void* d_out, int out_size)
{
    const float* thax_table = (const float*)d_in[0];
    const float* sine_table = (const float*)d_in[1];
    const float* rule_W     = (const float*)d_in[2];
    const float* rule_b     = (const float*)d_in[3];
    const float* eval_w     = (const float*)d_in[4];
    const float* eval_b     = (const float*)d_in[5];
    const float* pos_vals   = (const float*)d_in[6];
    const float* neg_vals   = (const float*)d_in[7];
    const int*   init_thax  = (const int*)d_in[8];
    const int*   init_sine  = (const int*)d_in[9];
    const int*   parents    = (const int*)d_in[10];
    const int*   rules      = (const int*)d_in[11];

    (void)in_sizes; (void)n_in; (void)out_size;

    cudaFuncSetAttribute(level_kernel,
                         cudaFuncAttributeMaxDynamicSharedMemorySize, LEVEL_SMEM);

    init_embed_kernel<<<2048, 256>>>((const float4*)thax_table,
                                     (const float4*)sine_table,
                                     init_thax, init_sine);
    group_kernel<<<LVLS, 256>>>(rules);
    for (int lvl = 0; lvl < LVLS; lvl++)
        level_kernel<<<N_RULES, 256, LEVEL_SMEM>>>(rule_W, rule_b, parents, lvl);
    eval_kernel<<<EVAL_BLOCKS, 256>>>(eval_w, eval_b, pos_vals, neg_vals);
    final_kernel<<<1, 32>>>((float*)d_out);
}

// round 2
// speedup vs baseline: 1.0223x; 1.0223x over previous
#include <cuda_runtime.h>

#define D        128
#define N_INIT   100000
#define LVLS     64
#define M        4096
#define N_RULES  256
#define N_TOT    (N_INIT + LVLS * M)

#define EVAL_BLOCKS 1024

typedef unsigned long long ull;

// smem layout for level kernel (all sizes in bytes)
// Wt: 64 rows (col-pairs) x 258 pairs (pitch) x 8B   = 132096
// PE: 16 rows (nodes)     x 258 pairs (pitch) x 8B   =  33024
// bias: 128 floats                                    =    512
// meta: 48 ints                                       =    192
#define PITCH       258
#define SM_WT_ULL   (64 * PITCH)
#define SM_PE_ULL   (16 * PITCH)
#define LEVEL_SMEM  ((SM_WT_ULL + SM_PE_ULL) * 8 + 512 + 192)

__device__ float g_store[(size_t)N_TOT * D];     // node embeddings
__device__ int   g_order[LVLS * M];              // node ids grouped by rule
__device__ int   g_ruleoff[LVLS * (N_RULES + 1)];
__device__ float g_partial[EVAL_BLOCKS * 6];     // A, B, posOK, negOK, sum_pos, sum_neg

__device__ __forceinline__ ull pack2(float lo, float hi) {
    return ((ull)__float_as_uint(hi) << 32) | (ull)__float_as_uint(lo);
}
__device__ __forceinline__ ull dup2(float v) {
    unsigned int u = __float_as_uint(v);
    return ((ull)u << 32) | (ull)u;
}

// ---------------------------------------------------------------------------
// K1: init embeddings  store[i] = thax_table[init_thax[i]] + sine_table[init_sine[i]]
// ---------------------------------------------------------------------------
__global__ void init_embed_kernel(const float4* __restrict__ thax,
                                  const float4* __restrict__ sine,
                                  const int* __restrict__ it,
                                  const int* __restrict__ is)
{
    int tid = blockIdx.x * blockDim.x + threadIdx.x;
    int total = N_INIT * (D / 4);
    float4* st = (float4*)g_store;
    for (int k = tid; k < total; k += gridDim.x * blockDim.x) {
        int i = k >> 5;        // D/4 = 32 chunks per node
        int c = k & 31;
        float4 a = thax[(size_t)it[i] * 32 + c];
        float4 b = sine[(size_t)is[i] * 32 + c];
        st[(size_t)i * 32 + c] = make_float4(a.x + b.x, a.y + b.y, a.z + b.z, a.w + b.w);
    }
}

// ---------------------------------------------------------------------------
// K2: group nodes by rule (counting sort), one block per level
// ---------------------------------------------------------------------------
__global__ void group_kernel(const int* __restrict__ rules)
{
    int lvl = blockIdx.x;
    __shared__ int counts[N_RULES];
    __shared__ int offs[N_RULES + 1];
    __shared__ int cursor[N_RULES];

    for (int r = threadIdx.x; r < N_RULES; r += blockDim.x) counts[r] = 0;
    __syncthreads();
    for (int j = threadIdx.x; j < M; j += blockDim.x)
        atomicAdd(&counts[rules[lvl * M + j]], 1);
    __syncthreads();
    if (threadIdx.x == 0) {
        int s = 0;
        for (int r = 0; r < N_RULES; r++) { offs[r] = s; s += counts[r]; }
        offs[N_RULES] = s;
    }
    __syncthreads();
    for (int r = threadIdx.x; r < N_RULES; r += blockDim.x) cursor[r] = offs[r];
    for (int r = threadIdx.x; r <= N_RULES; r += blockDim.x)
        g_ruleoff[lvl * (N_RULES + 1) + r] = offs[r];
    __syncthreads();
    for (int j = threadIdx.x; j < M; j += blockDim.x) {
        int r = rules[lvl * M + j];
        int p = atomicAdd(&cursor[r], 1);
        g_order[lvl * M + p] = j;   // order within a rule is arbitrary; per-node math is independent
    }
}

// ---------------------------------------------------------------------------
// K3 inner loop: NT = number of live node groups for this thread (1..4).
// Thread (o2, gg) accumulates nodes s = gg + 4t for t < NT, output col pair
// (2*o2, 2*o2+1). Per 2k: 1 Wt LDS.128 + NT PE LDS.128 + 2*NT FFMA2.
// ---------------------------------------------------------------------------
template<int NT>
__device__ __forceinline__ void compute_tile(const ull* __restrict__ Wrow,
                                             const ull* __restrict__ PEb,
                                             int gg, ull* acc)
{
    #pragma unroll
    for (int t = 0; t < NT; t++) acc[t] = 0ull;

    #pragma unroll 4
    for (int kk = 0; kk < 128; kk++) {
        ulonglong2 w = *(const ulonglong2*)(Wrow + 2 * kk);
        #pragma unroll
        for (int t = 0; t < NT; t++) {
            ulonglong2 p = *(const ulonglong2*)(PEb + (size_t)(gg + 4 * t) * PITCH + 2 * kk);
            asm("fma.rn.f32x2 %0, %1, %2, %0;" : "+l"(acc[t]) : "l"(p.x), "l"(w.x));
            asm("fma.rn.f32x2 %0, %1, %2, %0;" : "+l"(acc[t]) : "l"(p.y), "l"(w.y));
        }
    }
}

// ---------------------------------------------------------------------------
// K3: one level. Grid = 128 CTAs x 256 threads; CTA b handles rules b, b+128.
// W staged in smem transposed+column-paired; PE staged duplicated.
// ---------------------------------------------------------------------------
__global__ void __launch_bounds__(256, 1)
level_kernel(const float* __restrict__ rule_W,
             const float* __restrict__ rule_b,
             const int* __restrict__ parents,
             int lvl)
{
    extern __shared__ unsigned char sm[];
    ull*   Wt   = (ull*)sm;                                     // [64][PITCH]
    ull*   PE   = (ull*)(sm + SM_WT_ULL * 8);                   // [16][PITCH]
    float* bsh  = (float*)(sm + (SM_WT_ULL + SM_PE_ULL) * 8);   // [128]
    int*   meta = (int*)(bsh + 128);                            // [48]

    int tid = threadIdx.x;
    int o2  = tid & 63;        // col pair index
    int gg  = tid >> 6;        // node group 0..3

    for (int rr = 0; rr < 2; rr++) {
        int r = blockIdx.x + rr * 128;
        int start = g_ruleoff[lvl * (N_RULES + 1) + r];
        int end   = g_ruleoff[lvl * (N_RULES + 1) + r + 1];
        if (start == end) continue;

        __syncthreads();   // previous rule's compute done before overwriting Wt

        // stage W: Wt[2q][k] = (W[k][4q], W[k][4q+1]); Wt[2q+1][k] = (W[k][4q+2], W[k][4q+3])
        {
            const float4* Wg = (const float4*)(rule_W + (size_t)r * 256 * 128);
            #pragma unroll 4
            for (int idx = tid; idx < 8192; idx += 256) {
                int k = idx >> 5, q = idx & 31;
                float4 w = Wg[idx];
                Wt[(size_t)(2 * q) * PITCH + k]     = pack2(w.x, w.y);
                Wt[(size_t)(2 * q + 1) * PITCH + k] = pack2(w.z, w.w);
            }
            if (tid < 128) bsh[tid] = rule_b[r * 128 + tid];
        }

        for (int base = start; base < end; base += 16) {
            int nact = min(16, end - base);

            if (tid < 16) {
                int slot = base + tid;
                int j = -1, p0 = 0, p1 = 0;
                if (slot < end) {
                    j  = g_order[lvl * M + slot];
                    p0 = parents[((size_t)lvl * M + j) * 2 + 0];
                    p1 = parents[((size_t)lvl * M + j) * 2 + 1];
                }
                meta[tid]      = j;
                meta[16 + tid] = p0;
                meta[32 + tid] = p1;
            }
            __syncthreads();   // meta visible; W staged (first tile); prior compute done

            // stage PE: rows rw = 2*s + h; PE[s][h*128 + di] = dup(store[parent_h][di])
            {
                int di = tid & 127;
                #pragma unroll 4
                for (int rw = (tid >> 7); rw < 2 * nact; rw += 2) {
                    int s = rw >> 1, h = rw & 1;
                    int p = meta[16 + 16 * h + s];
                    float v = g_store[(size_t)p * D + di];
                    PE[(size_t)s * PITCH + h * 128 + di] = dup2(v);
                }
            }
            __syncthreads();   // PE ready

            int nt = (nact - gg + 3) >> 2;   // # of t with gg+4t < nact (uniform per warp)
            if (nt > 0) {
                ull acc[4];
                const ull* Wrow = Wt + (size_t)o2 * PITCH;
                switch (nt) {
                    case 4: compute_tile<4>(Wrow, PE, gg, acc); break;
                    case 3: compute_tile<3>(Wrow, PE, gg, acc); break;
                    case 2: compute_tile<2>(Wrow, PE, gg, acc); break;
                    default: compute_tile<1>(Wrow, PE, gg, acc); break;
                }

                float b0 = bsh[2 * o2], b1 = bsh[2 * o2 + 1];
                #pragma unroll
                for (int t = 0; t < 4; t++) {
                    if (t < nt) {
                        int j = meta[gg + 4 * t];
                        float x = __uint_as_float((unsigned int)(acc[t] & 0xffffffffull));
                        float y = __uint_as_float((unsigned int)(acc[t] >> 32));
                        x = fmaxf(x + b0, 0.0f);
                        y = fmaxf(y + b1, 0.0f);
                        size_t node = (size_t)N_INIT + (size_t)lvl * M + j;
                        ((float2*)(g_store + node * D))[o2] = make_float2(x, y);
                    }
                }
            }
            __syncthreads();   // compute done before next tile's PE restage
        }
    }
}

// ---------------------------------------------------------------------------
// K4: eval + partial reductions (deterministic: fixed grid, fixed slots)
// ---------------------------------------------------------------------------
__global__ void eval_kernel(const float* __restrict__ eval_w,
                            const float* __restrict__ eval_b,
                            const float* __restrict__ pos_vals,
                            const float* __restrict__ neg_vals)
{
    __shared__ float4 sw[32];
    __shared__ float  wacc[8][6];
    if (threadIdx.x < 32) sw[threadIdx.x] = ((const float4*)eval_w)[threadIdx.x];
    __syncthreads();

    int wid  = threadIdx.x >> 5;
    int lane = threadIdx.x & 31;
    int gw     = blockIdx.x * 8 + wid;
    int nwarps = EVAL_BLOCKS * 8;
    float eb = eval_b[0];
    float4 w4 = sw[lane];

    float A = 0.f, B = 0.f, pok = 0.f, nok = 0.f, spv = 0.f, snv = 0.f;

    for (size_t node = gw; node < (size_t)N_TOT; node += nwarps) {
        float4 v = ((const float4*)(g_store + node * D))[lane];
        float d = v.x * w4.x + v.y * w4.y + v.z * w4.z + v.w * w4.w;
        #pragma unroll
        for (int off = 16; off; off >>= 1) d += __shfl_down_sync(0xffffffffu, d, off);
        if (lane == 0) {
            float l  = d + eb;
            float pv = pos_vals[node], nv = neg_vals[node];
            float spn = log1pf(expf(-fabsf(l)));        // softplus(-|l|)
            float sp_pos = spn + fmaxf(l, 0.f);         // softplus(l)
            float sp_neg = spn + fmaxf(-l, 0.f);        // softplus(-l)
            A += pv * sp_neg;
            B += nv * sp_pos;
            if (l >= 0.f) pok += pv; else nok += nv;
            spv += pv;
            snv += nv;
        }
    }

    if (lane == 0) {
        wacc[wid][0] = A;   wacc[wid][1] = B;
        wacc[wid][2] = pok; wacc[wid][3] = nok;
        wacc[wid][4] = spv; wacc[wid][5] = snv;
    }
    __syncthreads();
    if (threadIdx.x == 0) {
        float o[6] = {0, 0, 0, 0, 0, 0};
        for (int w = 0; w < 8; w++)
            for (int k = 0; k < 6; k++) o[k] += wacc[w][k];
        for (int k = 0; k < 6; k++) g_partial[blockIdx.x * 6 + k] = o[k];
    }
}

// ---------------------------------------------------------------------------
// K5: final deterministic combine; loss = (sum_neg/sum_pos)*A + B
// ---------------------------------------------------------------------------
__global__ void final_kernel(float* __restrict__ out)
{
    if (blockIdx.x == 0 && threadIdx.x == 0) {
        float A = 0.f, B = 0.f, pok = 0.f, nok = 0.f, spv = 0.f, snv = 0.f;
        for (int b = 0; b < EVAL_BLOCKS; b++) {
            A   += g_partial[b * 6 + 0];
            B   += g_partial[b * 6 + 1];
            pok += g_partial[b * 6 + 2];
            nok += g_partial[b * 6 + 3];
            spv += g_partial[b * 6 + 4];
            snv += g_partial[b * 6 + 5];
        }
        float pw = snv / spv;
        out[0] = pw * A + B;
        out[1] = pok;
        out[2] = nok;
    }
}

// ---------------------------------------------------------------------------
extern "C" void kernel_launch(void* const* d_in, const int* in_sizes, int n_in,
                              void* d_out, int out_size)
{
    const float* thax_table = (const float*)d_in[0];
    const float* sine_table = (const float*)d_in[1];
    const float* rule_W     = (const float*)d_in[2];
    const float* rule_b     = (const float*)d_in[3];
    const float* eval_w     = (const float*)d_in[4];
    const float* eval_b     = (const float*)d_in[5];
    const float* pos_vals   = (const float*)d_in[6];
    const float* neg_vals   = (const float*)d_in[7];
    const int*   init_thax  = (const int*)d_in[8];
    const int*   init_sine  = (const int*)d_in[9];
    const int*   parents    = (const int*)d_in[10];
    const int*   rules      = (const int*)d_in[11];

    (void)in_sizes; (void)n_in; (void)out_size;

    cudaFuncSetAttribute(level_kernel,
                         cudaFuncAttributeMaxDynamicSharedMemorySize, LEVEL_SMEM);

    init_embed_kernel<<<2048, 256>>>((const float4*)thax_table,
                                     (const float4*)sine_table,
                                     init_thax, init_sine);
    group_kernel<<<LVLS, 256>>>(rules);
    for (int lvl = 0; lvl < LVLS; lvl++)
        level_kernel<<<128, 256, LEVEL_SMEM>>>(rule_W, rule_b, parents, lvl);
    eval_kernel<<<EVAL_BLOCKS, 256>>>(eval_w, eval_b, pos_vals, neg_vals);
    final_kernel<<<1, 32>>>((float*)d_out);
}

// round 3
// speedup vs baseline: 1.5965x; 1.5616x over previous
#include <cuda_runtime.h>

#define D        128
#define N_INIT   100000
#define LVLS     64
#define M        4096
#define N_RULES  256
#define N_TOT    (N_INIT + LVLS * M)

#define NCTA     128          // persistent CTAs, 1 per SM, single wave (<=148)
#define TILE     24           // nodes per tile
#define NCHUNK   8            // 256 k-values / 32 per chunk
#define EVAL_BLOCKS 1024

typedef unsigned long long ull;

// ---- smem layout (ull units) ----
#define WPITCH   258          // Wres row pitch (256 k + pad, conflict-free LDS.128)
#define CPITCH   34           // chunk row pitch (32 k + pad)
#define PPITCH   258          // PE row pitch
#define OFF_WRES 0
#define OFF_WS   (64 * WPITCH)                    // 2 chunk buffers, each 64*CPITCH
#define OFF_PE   (OFF_WS + 2 * 64 * CPITCH)
#define ULL_TOT  (OFF_PE + TILE * PPITCH)
#define OFF_BIASA (ULL_TOT * 8)                   // bytes
#define OFF_BIASB (OFF_BIASA + 512)
#define OFF_META  (OFF_BIASB + 512)               // 72 ints
#define LEVEL_SMEM (OFF_META + 96 * 4)

__device__ float g_store[(size_t)N_TOT * D];
__device__ int   g_order[LVLS * M];
__device__ int   g_ruleoff[LVLS * (N_RULES + 1)];
__device__ int   g_assign[LVLS * NCTA];          // streamed rule per CTA per level
__device__ float g_partial[EVAL_BLOCKS * 6];
__device__ unsigned g_arrive;
__device__ unsigned g_epoch;

__device__ __forceinline__ ull pack2(float lo, float hi) {
    return ((ull)__float_as_uint(hi) << 32) | (ull)__float_as_uint(lo);
}
__device__ __forceinline__ ull dup2(float v) {
    unsigned int u = __float_as_uint(v);
    return ((ull)u << 32) | (ull)u;
}

// ---------------------------------------------------------------------------
// K1: init embeddings
// ---------------------------------------------------------------------------
__global__ void init_embed_kernel(const float4* __restrict__ thax,
                                  const float4* __restrict__ sine,
                                  const int* __restrict__ it,
                                  const int* __restrict__ is)
{
    int tid = blockIdx.x * blockDim.x + threadIdx.x;
    int total = N_INIT * (D / 4);
    float4* st = (float4*)g_store;
    for (int k = tid; k < total; k += gridDim.x * blockDim.x) {
        int i = k >> 5;
        int c = k & 31;
        float4 a = thax[(size_t)it[i] * 32 + c];
        float4 b = sine[(size_t)is[i] * 32 + c];
        st[(size_t)i * 32 + c] = make_float4(a.x + b.x, a.y + b.y, a.z + b.z, a.w + b.w);
    }
}

// ---------------------------------------------------------------------------
// K2: group nodes by rule + balanced pairing of resident/streamed rules
// ---------------------------------------------------------------------------
__global__ void group_kernel(const int* __restrict__ rules)
{
    int lvl = blockIdx.x;
    int tid = threadIdx.x;
    __shared__ int counts[N_RULES];
    __shared__ int offs[N_RULES + 1];
    __shared__ int cursor[N_RULES];
    __shared__ int sA[128], sB[128];

    for (int r = tid; r < N_RULES; r += blockDim.x) counts[r] = 0;
    __syncthreads();
    for (int j = tid; j < M; j += blockDim.x)
        atomicAdd(&counts[rules[lvl * M + j]], 1);
    __syncthreads();
    if (tid == 0) {
        int s = 0;
        for (int r = 0; r < N_RULES; r++) { offs[r] = s; s += counts[r]; }
        offs[N_RULES] = s;
    }
    __syncthreads();
    for (int r = tid; r < N_RULES; r += blockDim.x) cursor[r] = offs[r];
    for (int r = tid; r <= N_RULES; r += blockDim.x)
        g_ruleoff[lvl * (N_RULES + 1) + r] = offs[r];
    __syncthreads();
    for (int j = tid; j < M; j += blockDim.x) {
        int r = rules[lvl * M + j];
        int p = atomicAdd(&cursor[r], 1);
        g_order[lvl * M + p] = j;
    }

    // --- balanced pairing: sort rules 0..127 and 128..255 by count, pair reversed
    {
        int h = tid & 127;
        if (tid < 128) sA[h] = (min(counts[h], 255) << 8) | h;
        else           sB[h] = (min(counts[128 + h], 255) << 8) | h;
        __syncthreads();
        for (int k = 2; k <= 128; k <<= 1) {
            for (int j = k >> 1; j > 0; j >>= 1) {
                int* arr = (tid < 128) ? sA : sB;
                int ixj = h ^ j;
                if (ixj > h) {
                    int a = arr[h], b = arr[ixj];
                    bool up = ((h & k) == 0);
                    if ((a > b) == up) { arr[h] = b; arr[ixj] = a; }
                }
                __syncthreads();
            }
        }
        if (tid < 128) {
            int rres = sA[tid] & 0xff;                 // ascending count
            int rstr = 128 + (sB[127 - tid] & 0xff);   // descending count
            g_assign[lvl * NCTA + rres] = rstr;
        }
    }
}

// ---------------------------------------------------------------------------
// compute kernels (inner loops)
// ---------------------------------------------------------------------------
template<int NT>
__device__ __forceinline__ void compute_full(const ull* __restrict__ Wrow,
                                             const ull* __restrict__ PEb,
                                             ull* acc)
{
    const ull* pe[NT];
    #pragma unroll
    for (int t = 0; t < NT; t++) pe[t] = PEb + (size_t)t * 4 * PPITCH;
    #pragma unroll 8
    for (int i = 0; i < 128; i++) {
        ulonglong2 w = *(const ulonglong2*)(Wrow + 2 * i);
        #pragma unroll
        for (int t = 0; t < NT; t++) {
            ulonglong2 p = *(const ulonglong2*)(pe[t] + 2 * i);
            asm("fma.rn.f32x2 %0, %1, %2, %0;" : "+l"(acc[t]) : "l"(p.x), "l"(w.x));
            asm("fma.rn.f32x2 %0, %1, %2, %0;" : "+l"(acc[t]) : "l"(p.y), "l"(w.y));
        }
    }
}

template<int NT>
__device__ __forceinline__ void compute_chunk(const ull* __restrict__ Wrow,
                                              const ull* __restrict__ PEb,
                                              ull* acc)
{
    const ull* pe[NT];
    #pragma unroll
    for (int t = 0; t < NT; t++) pe[t] = PEb + (size_t)t * 4 * PPITCH;
    #pragma unroll 8
    for (int i = 0; i < 16; i++) {
        ulonglong2 w = *(const ulonglong2*)(Wrow + 2 * i);
        #pragma unroll
        for (int t = 0; t < NT; t++) {
            ulonglong2 p = *(const ulonglong2*)(pe[t] + 2 * i);
            asm("fma.rn.f32x2 %0, %1, %2, %0;" : "+l"(acc[t]) : "l"(p.x), "l"(w.x));
            asm("fma.rn.f32x2 %0, %1, %2, %0;" : "+l"(acc[t]) : "l"(p.y), "l"(w.y));
        }
    }
}

// issue one 32-k W chunk of rule r as cp.async 8B transfers (transposed layout)
__device__ __forceinline__ void issue_chunk(ull* dst, const float* __restrict__ rule_W,
                                            int r, int c, int tid)
{
    const char* src = (const char*)rule_W + (size_t)r * 131072 + (size_t)c * 16384;
    #pragma unroll
    for (int i = 0; i < 8; i++) {
        int idx = tid + i * 256;
        int e = idx >> 1, half = idx & 1;
        int k = e >> 5, q = e & 31;
        const char* s = src + k * 512 + q * 16 + half * 8;
        ull* d = dst + (size_t)(2 * q + half) * CPITCH + k;
        unsigned daddr = (unsigned)__cvta_generic_to_shared(d);
        asm volatile("cp.async.ca.shared.global [%0], [%1], 8;" :: "r"(daddr), "l"(s));
    }
}

__device__ __forceinline__ void grid_barrier(unsigned target)
{
    __syncthreads();
    if (threadIdx.x == 0) {
        __threadfence();
        unsigned a = atomicAdd(&g_arrive, 1);
        if (a == NCTA - 1) {
            *((volatile unsigned*)&g_arrive) = 0;
            __threadfence();
            atomicAdd(&g_epoch, 1);
        } else {
            while (*((volatile unsigned*)&g_epoch) < target) __nanosleep(64);
            __threadfence();
        }
    }
    __syncthreads();
}

// ---------------------------------------------------------------------------
// K3: persistent kernel over all 64 levels
// ---------------------------------------------------------------------------
__global__ void __launch_bounds__(256, 1)
levels_kernel(const float* __restrict__ rule_W,
              const float* __restrict__ rule_b,
              const int* __restrict__ parents)
{
    extern __shared__ ull sm[];
    ull*   Wres  = sm + OFF_WRES;
    ull*   Ws0   = sm + OFF_WS;
    ull*   Ws1   = Ws0 + 64 * CPITCH;
    ull*   PE    = sm + OFF_PE;
    float* biasA = (float*)((char*)sm + OFF_BIASA);
    float* biasB = (float*)((char*)sm + OFF_BIASB);
    int*   meta  = (int*)((char*)sm + OFF_META);

    int tid  = threadIdx.x;
    int b    = blockIdx.x;
    int o2   = tid & 63;
    int gg   = tid >> 6;
    int warp = tid >> 5;
    int lane = tid & 31;

    unsigned epoch_base = *((volatile unsigned*)&g_epoch);  // safe: can't advance
                                                            // until all CTAs arrive

    // stage resident W (rule b) + biasA, once
    {
        const float4* Wg = (const float4*)(rule_W + (size_t)b * 32768);
        #pragma unroll 4
        for (int idx = tid; idx < 8192; idx += 256) {
            int k = idx >> 5, q = idx & 31;
            float4 w = Wg[idx];
            Wres[(size_t)(2 * q) * WPITCH + k]     = pack2(w.x, w.y);
            Wres[(size_t)(2 * q + 1) * WPITCH + k] = pack2(w.z, w.w);
        }
        if (tid < 128) biasA[tid] = rule_b[b * 128 + tid];
    }

    for (int lvl = 0; lvl < LVLS; lvl++) {
        int rA = b;
        int rB = g_assign[lvl * NCTA + b];
        int startA = g_ruleoff[lvl * (N_RULES + 1) + rA];
        int endA   = g_ruleoff[lvl * (N_RULES + 1) + rA + 1];
        int startB = g_ruleoff[lvl * (N_RULES + 1) + rB];
        int endB   = g_ruleoff[lvl * (N_RULES + 1) + rB + 1];
        bool hasB  = endB > startB;

        // prefetch first two W chunks of streamed rule + its bias
        if (hasB) {
            issue_chunk(Ws0, rule_W, rB, 0, tid);
            asm volatile("cp.async.commit_group;" ::: "memory");
            issue_chunk(Ws1, rule_W, rB, 1, tid);
            asm volatile("cp.async.commit_group;" ::: "memory");
            if (tid < 128) biasB[tid] = rule_b[rB * 128 + tid];
        }

        // ---- rule A (resident W) ----
        for (int base = startA; base < endA; base += TILE) {
            int nact = min(TILE, endA - base);
            __syncthreads();
            if (tid < TILE) {
                int slot = base + tid;
                int j = -1, p0 = 0, p1 = 0;
                if (slot < endA) {
                    j  = g_order[lvl * M + slot];
                    p0 = parents[((size_t)lvl * M + j) * 2 + 0];
                    p1 = parents[((size_t)lvl * M + j) * 2 + 1];
                }
                meta[tid] = j; meta[TILE + tid] = p0; meta[2 * TILE + tid] = p1;
            }
            __syncthreads();
            for (int rw = warp; rw < 2 * nact; rw += 8) {
                int s = rw >> 1, h = rw & 1;
                int p = meta[TILE * (1 + h) + s];
                float4 v = __ldcg((const float4*)(g_store + (size_t)p * D) + lane);
                ull* dst = PE + (size_t)s * PPITCH + h * 128 + lane * 4;
                ((ulonglong2*)dst)[0] = make_ulonglong2(dup2(v.x), dup2(v.y));
                ((ulonglong2*)dst)[1] = make_ulonglong2(dup2(v.z), dup2(v.w));
            }
            __syncthreads();
            int nt = (nact > gg) ? ((nact - gg + 3) >> 2) : 0;
            if (nt > 0) {
                ull acc[6] = {0, 0, 0, 0, 0, 0};
                const ull* Wrow = Wres + (size_t)o2 * WPITCH;
                const ull* PEb  = PE + (size_t)gg * PPITCH;
                switch (nt) {
                    case 6: compute_full<6>(Wrow, PEb, acc); break;
                    case 5: compute_full<5>(Wrow, PEb, acc); break;
                    case 4: compute_full<4>(Wrow, PEb, acc); break;
                    case 3: compute_full<3>(Wrow, PEb, acc); break;
                    case 2: compute_full<2>(Wrow, PEb, acc); break;
                    default: compute_full<1>(Wrow, PEb, acc); break;
                }
                float b0 = biasA[2 * o2], b1 = biasA[2 * o2 + 1];
                #pragma unroll
                for (int t = 0; t < 6; t++) if (t < nt) {
                    int j = meta[gg + 4 * t];
                    float x = __uint_as_float((unsigned)(acc[t] & 0xffffffffull));
                    float y = __uint_as_float((unsigned)(acc[t] >> 32));
                    x = fmaxf(x + b0, 0.0f); y = fmaxf(y + b1, 0.0f);
                    size_t node = (size_t)N_INIT + (size_t)lvl * M + j;
                    ((float2*)(g_store + node * D))[o2] = make_float2(x, y);
                }
            }
        }

        // ---- rule B (streamed W, chunk-pipelined) ----
        if (hasB) {
            for (int base = startB; base < endB; base += TILE) {
                int nact = min(TILE, endB - base);
                if (base > startB) {       // rare 2nd tile: restream chunks 0,1
                    __syncthreads();
                    issue_chunk(Ws0, rule_W, rB, 0, tid);
                    asm volatile("cp.async.commit_group;" ::: "memory");
                    issue_chunk(Ws1, rule_W, rB, 1, tid);
                    asm volatile("cp.async.commit_group;" ::: "memory");
                }
                __syncthreads();
                if (tid < TILE) {
                    int slot = base + tid;
                    int j = -1, p0 = 0, p1 = 0;
                    if (slot < endB) {
                        j  = g_order[lvl * M + slot];
                        p0 = parents[((size_t)lvl * M + j) * 2 + 0];
                        p1 = parents[((size_t)lvl * M + j) * 2 + 1];
                    }
                    meta[tid] = j; meta[TILE + tid] = p0; meta[2 * TILE + tid] = p1;
                }
                __syncthreads();
                for (int rw = warp; rw < 2 * nact; rw += 8) {
                    int s = rw >> 1, h = rw & 1;
                    int p = meta[TILE * (1 + h) + s];
                    float4 v = __ldcg((const float4*)(g_store + (size_t)p * D) + lane);
                    ull* dst = PE + (size_t)s * PPITCH + h * 128 + lane * 4;
                    ((ulonglong2*)dst)[0] = make_ulonglong2(dup2(v.x), dup2(v.y));
                    ((ulonglong2*)dst)[1] = make_ulonglong2(dup2(v.z), dup2(v.w));
                }
                __syncthreads();

                int nt = (nact > gg) ? ((nact - gg + 3) >> 2) : 0;
                ull acc[6] = {0, 0, 0, 0, 0, 0};
                const ull* PEg = PE + (size_t)gg * PPITCH;

                for (int c = 0; c < NCHUNK; c++) {
                    asm volatile("cp.async.wait_group 1;" ::: "memory");
                    __syncthreads();              // chunk c landed for ALL threads
                    if (nt > 0) {
                        const ull* Wrow = ((c & 1) ? Ws1 : Ws0) + (size_t)o2 * CPITCH;
                        const ull* PEb  = PEg + 32 * c;
                        switch (nt) {
                            case 6: compute_chunk<6>(Wrow, PEb, acc); break;
                            case 5: compute_chunk<5>(Wrow, PEb, acc); break;
                            case 4: compute_chunk<4>(Wrow, PEb, acc); break;
                            case 3: compute_chunk<3>(Wrow, PEb, acc); break;
                            case 2: compute_chunk<2>(Wrow, PEb, acc); break;
                            default: compute_chunk<1>(Wrow, PEb, acc); break;
                        }
                    }
                    __syncthreads();              // done reading before refill
                    if (c + 2 < NCHUNK)
                        issue_chunk((c & 1) ? Ws1 : Ws0, rule_W, rB, c + 2, tid);
                    asm volatile("cp.async.commit_group;" ::: "memory");
                }

                if (nt > 0) {
                    float b0 = biasB[2 * o2], b1 = biasB[2 * o2 + 1];
                    #pragma unroll
                    for (int t = 0; t < 6; t++) if (t < nt) {
                        int j = meta[gg + 4 * t];
                        float x = __uint_as_float((unsigned)(acc[t] & 0xffffffffull));
                        float y = __uint_as_float((unsigned)(acc[t] >> 32));
                        x = fmaxf(x + b0, 0.0f); y = fmaxf(y + b1, 0.0f);
                        size_t node = (size_t)N_INIT + (size_t)lvl * M + j;
                        ((float2*)(g_store + node * D))[o2] = make_float2(x, y);
                    }
                }
            }
        }

        if (lvl != LVLS - 1) grid_barrier(epoch_base + lvl + 1);
    }
}

// ---------------------------------------------------------------------------
// K4: eval + partial reductions
// ---------------------------------------------------------------------------
__global__ void eval_kernel(const float* __restrict__ eval_w,
                            const float* __restrict__ eval_b,
                            const float* __restrict__ pos_vals,
                            const float* __restrict__ neg_vals)
{
    __shared__ float4 sw[32];
    __shared__ float  wacc[8][6];
    if (threadIdx.x < 32) sw[threadIdx.x] = ((const float4*)eval_w)[threadIdx.x];
    __syncthreads();

    int wid  = threadIdx.x >> 5;
    int lane = threadIdx.x & 31;
    int gw     = blockIdx.x * 8 + wid;
    int nwarps = EVAL_BLOCKS * 8;
    float eb = eval_b[0];
    float4 w4 = sw[lane];

    float A = 0.f, B = 0.f, pok = 0.f, nok = 0.f, spv = 0.f, snv = 0.f;

    for (size_t node = gw; node < (size_t)N_TOT; node += nwarps) {
        float4 v = ((const float4*)(g_store + node * D))[lane];
        float d = v.x * w4.x + v.y * w4.y + v.z * w4.z + v.w * w4.w;
        #pragma unroll
        for (int off = 16; off; off >>= 1) d += __shfl_down_sync(0xffffffffu, d, off);
        if (lane == 0) {
            float l  = d + eb;
            float pv = pos_vals[node], nv = neg_vals[node];
            float spn = log1pf(expf(-fabsf(l)));
            float sp_pos = spn + fmaxf(l, 0.f);
            float sp_neg = spn + fmaxf(-l, 0.f);
            A += pv * sp_neg;
            B += nv * sp_pos;
            if (l >= 0.f) pok += pv; else nok += nv;
            spv += pv;
            snv += nv;
        }
    }

    if (lane == 0) {
        wacc[wid][0] = A;   wacc[wid][1] = B;
        wacc[wid][2] = pok; wacc[wid][3] = nok;
        wacc[wid][4] = spv; wacc[wid][5] = snv;
    }
    __syncthreads();
    if (threadIdx.x == 0) {
        float o[6] = {0, 0, 0, 0, 0, 0};
        for (int w = 0; w < 8; w++)
            for (int k = 0; k < 6; k++) o[k] += wacc[w][k];
        for (int k = 0; k < 6; k++) g_partial[blockIdx.x * 6 + k] = o[k];
    }
}

__global__ void final_kernel(float* __restrict__ out)
{
    if (blockIdx.x == 0 && threadIdx.x == 0) {
        float A = 0.f, B = 0.f, pok = 0.f, nok = 0.f, spv = 0.f, snv = 0.f;
        for (int b = 0; b < EVAL_BLOCKS; b++) {
            A   += g_partial[b * 6 + 0];
            B   += g_partial[b * 6 + 1];
            pok += g_partial[b * 6 + 2];
            nok += g_partial[b * 6 + 3];
            spv += g_partial[b * 6 + 4];
            snv += g_partial[b * 6 + 5];
        }
        float pw = snv / spv;
        out[0] = pw * A + B;
        out[1] = pok;
        out[2] = nok;
    }
}

// ---------------------------------------------------------------------------
extern "C" void kernel_launch(void* const* d_in, const int* in_sizes, int n_in,
                              void* d_out, int out_size)
{
    const float* thax_table = (const float*)d_in[0];
    const float* sine_table = (const float*)d_in[1];
    const float* rule_W     = (const float*)d_in[2];
    const float* rule_b     = (const float*)d_in[3];
    const float* eval_w     = (const float*)d_in[4];
    const float* eval_b     = (const float*)d_in[5];
    const float* pos_vals   = (const float*)d_in[6];
    const float* neg_vals   = (const float*)d_in[7];
    const int*   init_thax  = (const int*)d_in[8];
    const int*   init_sine  = (const int*)d_in[9];
    const int*   parents    = (const int*)d_in[10];
    const int*   rules      = (const int*)d_in[11];

    (void)in_sizes; (void)n_in; (void)out_size;

    cudaFuncSetAttribute(levels_kernel,
                         cudaFuncAttributeMaxDynamicSharedMemorySize, LEVEL_SMEM);

    init_embed_kernel<<<2048, 256>>>((const float4*)thax_table,
                                     (const float4*)sine_table,
                                     init_thax, init_sine);
    group_kernel<<<LVLS, 256>>>(rules);
    levels_kernel<<<NCTA, 256, LEVEL_SMEM>>>(rule_W, rule_b, parents);
    eval_kernel<<<EVAL_BLOCKS, 256>>>(eval_w, eval_b, pos_vals, neg_vals);
    final_kernel<<<1, 32>>>((float*)d_out);
}

// round 5
// speedup vs baseline: 3.3376x; 2.0906x over previous
#include <cuda_runtime.h>
#include <cuda_bf16.h>
#include <cstdint>

#define D        128
#define N_INIT   100000
#define LVLS     64
#define M        4096
#define N_RULES  256
#define N_TOT    (N_INIT + LVLS * M)

#define NCTA     256           // persistent CTAs, 2 per SM, single wave
#define TILE_N   32
#define EVAL_BLOCKS 1024

// B smem pitch: 264 bf16 = 528 bytes (132 words -> bank shift 4/row, conflict-free)
#define BPITCH_B 528
// per-rule A-fragment image: 8 warps x 16 ksteps x 32 lanes x 32B (4 hi u32 + 4 lo u32)
#define WIMG_BYTES 131072

__device__ float g_store[(size_t)N_TOT * D];
__device__ int   g_order[LVLS * M];
__device__ int   g_ruleoff[LVLS * (N_RULES + 1)];
__device__ int   g_ticket[LVLS];
__device__ float g_partial[EVAL_BLOCKS * 6];
__device__ unsigned g_arrive;
__device__ unsigned g_epoch;
__device__ unsigned char g_Wimg[(size_t)N_RULES * WIMG_BYTES];

static __device__ __forceinline__ unsigned pack_bf16x2(float lo, float hi) {
    unsigned short a = __bfloat16_as_ushort(__float2bfloat16_rn(lo));
    unsigned short b = __bfloat16_as_ushort(__float2bfloat16_rn(hi));
    return (unsigned)a | ((unsigned)b << 16);
}
static __device__ __forceinline__ float bf16_hi_part(float v) {
    return __bfloat162float(__float2bfloat16_rn(v));
}

// ---------------------------------------------------------------------------
// K1: init embeddings
// ---------------------------------------------------------------------------
__global__ void init_embed_kernel(const float4* __restrict__ thax,
                                  const float4* __restrict__ sine,
                                  const int* __restrict__ it,
                                  const int* __restrict__ is)
{
    int tid = blockIdx.x * blockDim.x + threadIdx.x;
    int total = N_INIT * (D / 4);
    float4* st = (float4*)g_store;
    for (int k = tid; k < total; k += gridDim.x * blockDim.x) {
        int i = k >> 5;
        int c = k & 31;
        float4 a = thax[(size_t)it[i] * 32 + c];
        float4 b = sine[(size_t)is[i] * 32 + c];
        st[(size_t)i * 32 + c] = make_float4(a.x + b.x, a.y + b.y, a.z + b.z, a.w + b.w);
    }
}

// ---------------------------------------------------------------------------
// K1b: convert rule_W -> fragment-ordered bf16 hi/lo image.
// A[m][k] = rule_W[r][k][m]. Entry (w,kk,lane): 32B = {a0h,a1h,a2h,a3h, a0l..a3l}
//   a0 = (m0, k0|k0+1), a1 = (m0+8, .), a2 = (m0, k0+8|k0+9), a3 = (m0+8, k0+8..)
//   m0 = 16w + lane/4, k0 = 16kk + (lane%4)*2
// ---------------------------------------------------------------------------
__global__ void convw_kernel(const float* __restrict__ rule_W)
{
    extern __shared__ float Wsm[];            // [256][128]
    int r   = blockIdx.x;
    int tid = threadIdx.x;

    const float4* src = (const float4*)(rule_W + (size_t)r * 32768);
    #pragma unroll 4
    for (int i = tid; i < 8192; i += 256) ((float4*)Wsm)[i] = __ldg(src + i);
    __syncthreads();

    unsigned char* dst = g_Wimg + (size_t)r * WIMG_BYTES;
    for (int idx = tid; idx < 4096; idx += 256) {
        int lane = idx & 31, kk = (idx >> 5) & 15, w = idx >> 9;
        int m0 = w * 16 + (lane >> 2);
        int k0 = kk * 16 + (lane & 3) * 2;

        float v[8];
        v[0] = Wsm[(k0)     * 128 + m0];     v[1] = Wsm[(k0 + 1) * 128 + m0];
        v[2] = Wsm[(k0)     * 128 + m0 + 8]; v[3] = Wsm[(k0 + 1) * 128 + m0 + 8];
        v[4] = Wsm[(k0 + 8) * 128 + m0];     v[5] = Wsm[(k0 + 9) * 128 + m0];
        v[6] = Wsm[(k0 + 8) * 128 + m0 + 8]; v[7] = Wsm[(k0 + 9) * 128 + m0 + 8];

        unsigned h[4], l[4];
        #pragma unroll
        for (int j = 0; j < 4; j++) {
            float h0 = bf16_hi_part(v[2*j]),   h1 = bf16_hi_part(v[2*j+1]);
            h[j] = pack_bf16x2(h0, h1);
            l[j] = pack_bf16x2(v[2*j] - h0, v[2*j+1] - h1);
        }
        *(uint4*)(dst + (size_t)idx * 32)      = make_uint4(h[0], h[1], h[2], h[3]);
        *(uint4*)(dst + (size_t)idx * 32 + 16) = make_uint4(l[0], l[1], l[2], l[3]);
    }
}

// ---------------------------------------------------------------------------
// K2: group nodes by rule (counting sort) + reset ticket
// ---------------------------------------------------------------------------
__global__ void group_kernel(const int* __restrict__ rules)
{
    int lvl = blockIdx.x;
    int tid = threadIdx.x;
    __shared__ int counts[N_RULES];
    __shared__ int offs[N_RULES + 1];
    __shared__ int cursor[N_RULES];

    if (tid == 0) g_ticket[lvl] = 0;
    for (int r = tid; r < N_RULES; r += blockDim.x) counts[r] = 0;
    __syncthreads();
    for (int j = tid; j < M; j += blockDim.x)
        atomicAdd(&counts[rules[lvl * M + j]], 1);
    __syncthreads();
    if (tid == 0) {
        int s = 0;
        for (int r = 0; r < N_RULES; r++) { offs[r] = s; s += counts[r]; }
        offs[N_RULES] = s;
    }
    __syncthreads();
    for (int r = tid; r < N_RULES; r += blockDim.x) cursor[r] = offs[r];
    for (int r = tid; r <= N_RULES; r += blockDim.x)
        g_ruleoff[lvl * (N_RULES + 1) + r] = offs[r];
    __syncthreads();
    for (int j = tid; j < M; j += blockDim.x) {
        int r = rules[lvl * M + j];
        int p = atomicAdd(&cursor[r], 1);
        g_order[lvl * M + p] = j;
    }
}

// ---------------------------------------------------------------------------
// mma helpers
// ---------------------------------------------------------------------------
static __device__ __forceinline__ void mma16816(float* c, const uint4& a,
                                                unsigned b0, unsigned b1)
{
    asm volatile(
        "mma.sync.aligned.m16n8k16.row.col.f32.bf16.bf16.f32 "
        "{%0,%1,%2,%3}, {%4,%5,%6,%7}, {%8,%9}, {%0,%1,%2,%3};"
        : "+f"(c[0]), "+f"(c[1]), "+f"(c[2]), "+f"(c[3])
        : "r"(a.x), "r"(a.y), "r"(a.z), "r"(a.w), "r"(b0), "r"(b1));
}
static __device__ __forceinline__ void ldmat4(unsigned& r0, unsigned& r1,
                                              unsigned& r2, unsigned& r3, unsigned addr)
{
    asm volatile("ldmatrix.sync.aligned.m8n8.x4.shared.b16 {%0,%1,%2,%3}, [%4];"
                 : "=r"(r0), "=r"(r1), "=r"(r2), "=r"(r3) : "r"(addr));
}

__device__ __forceinline__ void grid_barrier(unsigned target)
{
    __syncthreads();
    if (threadIdx.x == 0) {
        __threadfence();
        unsigned a = atomicAdd(&g_arrive, 1);
        if (a == NCTA - 1) {
            *((volatile unsigned*)&g_arrive) = 0;
            __threadfence();
            atomicAdd(&g_epoch, 1);
        } else {
            while (*((volatile unsigned*)&g_epoch) < target) __nanosleep(32);
            __threadfence();
        }
    }
    __syncthreads();
}

// ---------------------------------------------------------------------------
// K3: persistent levels kernel, HMMA split-bf16 (4 terms)
// ---------------------------------------------------------------------------
__global__ void __launch_bounds__(256, 2)
levels_kernel(const float* __restrict__ rule_b,
              const int* __restrict__ parents)
{
    __shared__ __align__(16) unsigned char Bh[TILE_N * BPITCH_B];
    __shared__ __align__(16) unsigned char Bl[TILE_N * BPITCH_B];
    __shared__ int s_meta[96];
    __shared__ int s_ticket;

    int tid  = threadIdx.x;
    int wid  = tid >> 5;
    int lane = tid & 31;

    unsigned bh_base = (unsigned)__cvta_generic_to_shared(Bh);
    unsigned bl_base = (unsigned)__cvta_generic_to_shared(Bl);

    unsigned epoch_base = *((volatile unsigned*)&g_epoch);

    // per-lane ldmatrix row offsets (pair p: matrices {2p, klo},{2p, khi},{2p+1, klo},{2p+1, khi})
    int g    = lane >> 3;
    int row8 = lane & 7;
    unsigned lm_koff   = (unsigned)(g & 1) * 16;                       // bytes
    unsigned lm_n_p0   = (unsigned)((0 * 2 + (g >> 1)) * 8 + row8);    // pair 0 rows
    unsigned lm_n_p1   = (unsigned)((1 * 2 + (g >> 1)) * 8 + row8);    // pair 1 rows
    unsigned lm_off_p0 = lm_n_p0 * BPITCH_B + lm_koff;
    unsigned lm_off_p1 = lm_n_p1 * BPITCH_B + lm_koff;

    for (int lvl = 0; lvl < LVLS; lvl++) {
        const int* lro = g_ruleoff + lvl * (N_RULES + 1);
        for (;;) {
            if (tid == 0) s_ticket = atomicAdd(&g_ticket[lvl], 1);
            __syncthreads();
            int r = s_ticket;
            __syncthreads();
            if (r >= N_RULES) break;
            int start = lro[r], end = lro[r + 1];
            if (start == end) continue;

            for (int tb = start; tb < end; tb += TILE_N) {
                // meta
                if (tid < TILE_N) {
                    int slot = tb + tid;
                    int j = -1, p0 = 0, p1 = 0;
                    if (slot < end) {
                        j  = g_order[lvl * M + slot];
                        p0 = parents[((size_t)lvl * M + j) * 2 + 0];
                        p1 = parents[((size_t)lvl * M + j) * 2 + 1];
                    }
                    s_meta[tid] = j; s_meta[32 + tid] = p0; s_meta[64 + tid] = p1;
                }
                __syncthreads();

                // PE gather + split-bf16 into Bh/Bl ([n][k] row-major, pitch 528B)
                {
                    int s   = tid >> 3;        // node 0..31
                    int seg = tid & 7;         // 32-k segment
                    int j = s_meta[s];
                    if (j >= 0) {
                        int p    = (seg < 4) ? s_meta[32 + s] : s_meta[64 + s];
                        int poff = (seg & 3) * 32;
                        const float4* src = (const float4*)(g_store + (size_t)p * D + poff);
                        unsigned char* dh = Bh + s * BPITCH_B + seg * 64;
                        unsigned char* dl = Bl + s * BPITCH_B + seg * 64;
                        #pragma unroll
                        for (int q = 0; q < 8; q += 2) {
                            float4 f0 = __ldcg(src + q);
                            float4 f1 = __ldcg(src + q + 1);
                            float h0x = bf16_hi_part(f0.x), h0y = bf16_hi_part(f0.y);
                            float h0z = bf16_hi_part(f0.z), h0w = bf16_hi_part(f0.w);
                            float h1x = bf16_hi_part(f1.x), h1y = bf16_hi_part(f1.y);
                            float h1z = bf16_hi_part(f1.z), h1w = bf16_hi_part(f1.w);
                            *(uint2*)(dh + q * 8) =
                                make_uint2(pack_bf16x2(h0x, h0y), pack_bf16x2(h0z, h0w));
                            *(uint2*)(dh + q * 8 + 8) =
                                make_uint2(pack_bf16x2(h1x, h1y), pack_bf16x2(h1z, h1w));
                            *(uint2*)(dl + q * 8) =
                                make_uint2(pack_bf16x2(f0.x - h0x, f0.y - h0y),
                                           pack_bf16x2(f0.z - h0z, f0.w - h0w));
                            *(uint2*)(dl + q * 8 + 8) =
                                make_uint2(pack_bf16x2(f1.x - h1x, f1.y - h1y),
                                           pack_bf16x2(f1.z - h1z, f1.w - h1w));
                        }
                    }
                }
                __syncthreads();

                // compute: warp wid -> output rows 16*wid .. +15
                {
                    float acc[4][4];
                    #pragma unroll
                    for (int nb = 0; nb < 4; nb++)
                        #pragma unroll
                        for (int q = 0; q < 4; q++) acc[nb][q] = 0.0f;

                    const uint4* ai = (const uint4*)(g_Wimg + (size_t)r * WIMG_BYTES)
                                      + (size_t)((wid * 16) * 32 + lane) * 2;

                    #pragma unroll 4
                    for (int kk = 0; kk < 16; kk++) {
                        uint4 ah = __ldg(ai);
                        uint4 al = __ldg(ai + 1);
                        ai += 64;
                        unsigned kb = (unsigned)kk * 32;

                        unsigned bh0, bh1, bh2, bh3, bl0, bl1, bl2, bl3;
                        ldmat4(bh0, bh1, bh2, bh3, bh_base + lm_off_p0 + kb);
                        ldmat4(bl0, bl1, bl2, bl3, bl_base + lm_off_p0 + kb);
                        mma16816(acc[0], ah, bh0, bh1);
                        mma16816(acc[0], ah, bl0, bl1);
                        mma16816(acc[0], al, bh0, bh1);
                        mma16816(acc[0], al, bl0, bl1);
                        mma16816(acc[1], ah, bh2, bh3);
                        mma16816(acc[1], ah, bl2, bl3);
                        mma16816(acc[1], al, bh2, bh3);
                        mma16816(acc[1], al, bl2, bl3);

                        ldmat4(bh0, bh1, bh2, bh3, bh_base + lm_off_p1 + kb);
                        ldmat4(bl0, bl1, bl2, bl3, bl_base + lm_off_p1 + kb);
                        mma16816(acc[2], ah, bh0, bh1);
                        mma16816(acc[2], ah, bl0, bl1);
                        mma16816(acc[2], al, bh0, bh1);
                        mma16816(acc[2], al, bl0, bl1);
                        mma16816(acc[3], ah, bh2, bh3);
                        mma16816(acc[3], ah, bl2, bl3);
                        mma16816(acc[3], al, bh2, bh3);
                        mma16816(acc[3], al, bl2, bl3);
                    }

                    // epilogue: c0:(m_lo,n0) c1:(m_lo,n0+1) c2:(m_hi,n0) c3:(m_hi,n0+1)
                    int m_lo = wid * 16 + (lane >> 2);
                    int m_hi = m_lo + 8;
                    float bias_lo = __ldg(rule_b + r * 128 + m_lo);
                    float bias_hi = __ldg(rule_b + r * 128 + m_hi);
                    size_t lvlbase = (size_t)N_INIT + (size_t)lvl * M;

                    #pragma unroll
                    for (int nb = 0; nb < 4; nb++) {
                        int n0 = nb * 8 + (lane & 3) * 2;
                        int j0 = s_meta[n0], j1 = s_meta[n0 + 1];
                        if (j0 >= 0) {
                            g_store[(lvlbase + j0) * D + m_lo] = fmaxf(acc[nb][0] + bias_lo, 0.f);
                            g_store[(lvlbase + j0) * D + m_hi] = fmaxf(acc[nb][2] + bias_hi, 0.f);
                        }
                        if (j1 >= 0) {
                            g_store[(lvlbase + j1) * D + m_lo] = fmaxf(acc[nb][1] + bias_lo, 0.f);
                            g_store[(lvlbase + j1) * D + m_hi] = fmaxf(acc[nb][3] + bias_hi, 0.f);
                        }
                    }
                }
                __syncthreads();   // done with Bh/Bl/meta before next tile
            }
        }
        if (lvl != LVLS - 1) grid_barrier(epoch_base + lvl + 1);
    }
}

// ---------------------------------------------------------------------------
// K4: eval + partial reductions
// ---------------------------------------------------------------------------
__global__ void eval_kernel(const float* __restrict__ eval_w,
                            const float* __restrict__ eval_b,
                            const float* __restrict__ pos_vals,
                            const float* __restrict__ neg_vals)
{
    __shared__ float4 sw[32];
    __shared__ float  wacc[8][6];
    if (threadIdx.x < 32) sw[threadIdx.x] = ((const float4*)eval_w)[threadIdx.x];
    __syncthreads();

    int wid  = threadIdx.x >> 5;
    int lane = threadIdx.x & 31;
    int gw     = blockIdx.x * 8 + wid;
    int nwarps = EVAL_BLOCKS * 8;
    float eb = eval_b[0];
    float4 w4 = sw[lane];

    float A = 0.f, B = 0.f, pok = 0.f, nok = 0.f, spv = 0.f, snv = 0.f;

    for (size_t node = gw; node < (size_t)N_TOT; node += nwarps) {
        float4 v = ((const float4*)(g_store + node * D))[lane];
        float d = v.x * w4.x + v.y * w4.y + v.z * w4.z + v.w * w4.w;
        #pragma unroll
        for (int off = 16; off; off >>= 1) d += __shfl_down_sync(0xffffffffu, d, off);
        if (lane == 0) {
            float l  = d + eb;
            float pv = pos_vals[node], nv = neg_vals[node];
            float spn = log1pf(expf(-fabsf(l)));
            float sp_pos = spn + fmaxf(l, 0.f);
            float sp_neg = spn + fmaxf(-l, 0.f);
            A += pv * sp_neg;
            B += nv * sp_pos;
            if (l >= 0.f) pok += pv; else nok += nv;
            spv += pv;
            snv += nv;
        }
    }

    if (lane == 0) {
        wacc[wid][0] = A;   wacc[wid][1] = B;
        wacc[wid][2] = pok; wacc[wid][3] = nok;
        wacc[wid][4] = spv; wacc[wid][5] = snv;
    }
    __syncthreads();
    if (threadIdx.x == 0) {
        float o[6] = {0, 0, 0, 0, 0, 0};
        for (int w = 0; w < 8; w++)
            for (int k = 0; k < 6; k++) o[k] += wacc[w][k];
        for (int k = 0; k < 6; k++) g_partial[blockIdx.x * 6 + k] = o[k];
    }
}

__global__ void final_kernel(float* __restrict__ out)
{
    if (blockIdx.x == 0 && threadIdx.x == 0) {
        float A = 0.f, B = 0.f, pok = 0.f, nok = 0.f, spv = 0.f, snv = 0.f;
        for (int b = 0; b < EVAL_BLOCKS; b++) {
            A   += g_partial[b * 6 + 0];
            B   += g_partial[b * 6 + 1];
            pok += g_partial[b * 6 + 2];
            nok += g_partial[b * 6 + 3];
            spv += g_partial[b * 6 + 4];
            snv += g_partial[b * 6 + 5];
        }
        float pw = snv / spv;
        out[0] = pw * A + B;
        out[1] = pok;
        out[2] = nok;
    }
}

// ---------------------------------------------------------------------------
extern "C" void kernel_launch(void* const* d_in, const int* in_sizes, int n_in,
                              void* d_out, int out_size)
{
    const float* thax_table = (const float*)d_in[0];
    const float* sine_table = (const float*)d_in[1];
    const float* rule_W     = (const float*)d_in[2];
    const float* rule_b     = (const float*)d_in[3];
    const float* eval_w     = (const float*)d_in[4];
    const float* eval_b     = (const float*)d_in[5];
    const float* pos_vals   = (const float*)d_in[6];
    const float* neg_vals   = (const float*)d_in[7];
    const int*   init_thax  = (const int*)d_in[8];
    const int*   init_sine  = (const int*)d_in[9];
    const int*   parents    = (const int*)d_in[10];
    const int*   rules      = (const int*)d_in[11];

    (void)in_sizes; (void)n_in; (void)out_size;

    cudaFuncSetAttribute(convw_kernel,
                         cudaFuncAttributeMaxDynamicSharedMemorySize, 131072);

    init_embed_kernel<<<2048, 256>>>((const float4*)thax_table,
                                     (const float4*)sine_table,
                                     init_thax, init_sine);
    convw_kernel<<<N_RULES, 256, 131072>>>(rule_W);
    group_kernel<<<LVLS, 256>>>(rules);
    levels_kernel<<<NCTA, 256>>>(rule_b, parents);
    eval_kernel<<<EVAL_BLOCKS, 256>>>(eval_w, eval_b, pos_vals, neg_vals);
    final_kernel<<<1, 32>>>((float*)d_out);
}

// round 6
// speedup vs baseline: 3.5669x; 1.0687x over previous
#include <cuda_runtime.h>
#include <cuda_bf16.h>
#include <cstdint>

#define D        128
#define N_INIT   100000
#define LVLS     64
#define M        4096
#define N_RULES  256
#define N_TOT    (N_INIT + LVLS * M)

#define NCTA     256           // persistent CTAs, 2 per SM, single wave; 16 groups of 16
#define TILE_N   32
#define MAXT     512           // max tiles per level (bound: 256 + 4096/32 = 384)
#define EVAL_BLOCKS 1024

// B smem pitch: 264 bf16 = 528 bytes (132 words -> bank shift 4/row, conflict-free)
#define BPITCH_B 528
// per-rule A-fragment image: 8 warps x 16 ksteps x 32 lanes x 32B (4 hi u32 + 4 lo u32)
#define WIMG_BYTES 131072

__device__ float g_store[(size_t)N_TOT * D];
__device__ int   g_order[LVLS * M];
__device__ int4  g_pack[LVLS * M];               // (j, p0, p1, 0) per grouped slot
__device__ unsigned g_tiledesc[LVLS * MAXT];     // r<<18 | base<<6 | nact
__device__ int   g_ntiles[LVLS];
__device__ float g_partial[EVAL_BLOCKS * 6];
__device__ unsigned g_grp[16];
__device__ unsigned g_root;
__device__ unsigned g_epoch;
__device__ unsigned char g_Wimg[(size_t)N_RULES * WIMG_BYTES];

static __device__ __forceinline__ unsigned pack_bf16x2(float lo, float hi) {
    unsigned short a = __bfloat16_as_ushort(__float2bfloat16_rn(lo));
    unsigned short b = __bfloat16_as_ushort(__float2bfloat16_rn(hi));
    return (unsigned)a | ((unsigned)b << 16);
}
static __device__ __forceinline__ float bf16_hi_part(float v) {
    return __bfloat162float(__float2bfloat16_rn(v));
}

// ---------------------------------------------------------------------------
// K1: init embeddings
// ---------------------------------------------------------------------------
__global__ void init_embed_kernel(const float4* __restrict__ thax,
                                  const float4* __restrict__ sine,
                                  const int* __restrict__ it,
                                  const int* __restrict__ is)
{
    int tid = blockIdx.x * blockDim.x + threadIdx.x;
    int total = N_INIT * (D / 4);
    float4* st = (float4*)g_store;
    for (int k = tid; k < total; k += gridDim.x * blockDim.x) {
        int i = k >> 5;
        int c = k & 31;
        float4 a = thax[(size_t)it[i] * 32 + c];
        float4 b = sine[(size_t)is[i] * 32 + c];
        st[(size_t)i * 32 + c] = make_float4(a.x + b.x, a.y + b.y, a.z + b.z, a.w + b.w);
    }
}

// ---------------------------------------------------------------------------
// K1b: convert rule_W -> fragment-ordered bf16 hi/lo image.
// ---------------------------------------------------------------------------
__global__ void convw_kernel(const float* __restrict__ rule_W)
{
    extern __shared__ float Wsm[];            // [256][128]
    int r   = blockIdx.x;
    int tid = threadIdx.x;

    const float4* src = (const float4*)(rule_W + (size_t)r * 32768);
    #pragma unroll 4
    for (int i = tid; i < 8192; i += 256) ((float4*)Wsm)[i] = __ldg(src + i);
    __syncthreads();

    unsigned char* dst = g_Wimg + (size_t)r * WIMG_BYTES;
    for (int idx = tid; idx < 4096; idx += 256) {
        int lane = idx & 31, kk = (idx >> 5) & 15, w = idx >> 9;
        int m0 = w * 16 + (lane >> 2);
        int k0 = kk * 16 + (lane & 3) * 2;

        float v[8];
        v[0] = Wsm[(k0)     * 128 + m0];     v[1] = Wsm[(k0 + 1) * 128 + m0];
        v[2] = Wsm[(k0)     * 128 + m0 + 8]; v[3] = Wsm[(k0 + 1) * 128 + m0 + 8];
        v[4] = Wsm[(k0 + 8) * 128 + m0];     v[5] = Wsm[(k0 + 9) * 128 + m0];
        v[6] = Wsm[(k0 + 8) * 128 + m0 + 8]; v[7] = Wsm[(k0 + 9) * 128 + m0 + 8];

        unsigned h[4], l[4];
        #pragma unroll
        for (int j = 0; j < 4; j++) {
            float h0 = bf16_hi_part(v[2*j]),   h1 = bf16_hi_part(v[2*j+1]);
            h[j] = pack_bf16x2(h0, h1);
            l[j] = pack_bf16x2(v[2*j] - h0, v[2*j+1] - h1);
        }
        *(uint4*)(dst + (size_t)idx * 32)      = make_uint4(h[0], h[1], h[2], h[3]);
        *(uint4*)(dst + (size_t)idx * 32 + 16) = make_uint4(l[0], l[1], l[2], l[3]);
    }
}

// ---------------------------------------------------------------------------
// K2: group by rule + pack (j,p0,p1) + build tile worklist + reset barrier
// ---------------------------------------------------------------------------
__global__ void group_kernel(const int* __restrict__ rules,
                             const int* __restrict__ parents)
{
    int lvl = blockIdx.x;
    int tid = threadIdx.x;
    __shared__ int counts[N_RULES];
    __shared__ int offs[N_RULES + 1];
    __shared__ int cursor[N_RULES];

    if (lvl == 0) {           // reset tree-barrier state each replay
        if (tid < 16) g_grp[tid] = 0;
        if (tid == 16) g_root = 0;
        if (tid == 17) g_epoch = 0;
    }

    for (int r = tid; r < N_RULES; r += blockDim.x) counts[r] = 0;
    __syncthreads();
    for (int j = tid; j < M; j += blockDim.x)
        atomicAdd(&counts[rules[lvl * M + j]], 1);
    __syncthreads();
    if (tid == 0) {
        int s = 0;
        for (int r = 0; r < N_RULES; r++) { offs[r] = s; s += counts[r]; }
        offs[N_RULES] = s;
    }
    __syncthreads();
    for (int r = tid; r < N_RULES; r += blockDim.x) cursor[r] = offs[r];
    __syncthreads();
    for (int j = tid; j < M; j += blockDim.x) {
        int r = rules[lvl * M + j];
        int p = atomicAdd(&cursor[r], 1);
        g_order[lvl * M + p] = j;
    }
    __syncthreads();

    // pack (j, p0, p1) per slot
    for (int slot = tid; slot < M; slot += blockDim.x) {
        int j = g_order[lvl * M + slot];
        int4 pk;
        pk.x = j;
        pk.y = parents[((size_t)lvl * M + j) * 2 + 0];
        pk.z = parents[((size_t)lvl * M + j) * 2 + 1];
        pk.w = 0;
        g_pack[lvl * M + slot] = pk;
    }

    // tile worklist
    if (tid == 0) {
        int t = 0;
        for (int r = 0; r < N_RULES; r++) {
            int c = counts[r];
            for (int bse = 0; bse < c; bse += TILE_N) {
                int na = min(TILE_N, c - bse);
                g_tiledesc[lvl * MAXT + t] =
                    ((unsigned)r << 18) | ((unsigned)(offs[r] + bse) << 6) | (unsigned)na;
                t++;
            }
        }
        g_ntiles[lvl] = t;
    }
}

// ---------------------------------------------------------------------------
// mma helpers
// ---------------------------------------------------------------------------
static __device__ __forceinline__ void mma16816(float* c, const uint4& a,
                                                unsigned b0, unsigned b1)
{
    asm volatile(
        "mma.sync.aligned.m16n8k16.row.col.f32.bf16.bf16.f32 "
        "{%0,%1,%2,%3}, {%4,%5,%6,%7}, {%8,%9}, {%0,%1,%2,%3};"
        : "+f"(c[0]), "+f"(c[1]), "+f"(c[2]), "+f"(c[3])
        : "r"(a.x), "r"(a.y), "r"(a.z), "r"(a.w), "r"(b0), "r"(b1));
}
static __device__ __forceinline__ void ldmat4(unsigned& r0, unsigned& r1,
                                              unsigned& r2, unsigned& r3, unsigned addr)
{
    asm volatile("ldmatrix.sync.aligned.m8n8.x4.shared.b16 {%0,%1,%2,%3}, [%4];"
                 : "=r"(r0), "=r"(r1), "=r"(r2), "=r"(r3) : "r"(addr));
}

// two-level tree barrier: 16 groups x 16 CTAs, monotonic counters
__device__ __forceinline__ void grid_barrier(unsigned target)
{
    __syncthreads();
    if (threadIdx.x == 0) {
        __threadfence();
        unsigned g = blockIdx.x >> 4;
        unsigned v = atomicAdd(&g_grp[g], 1u);
        if ((v & 15u) == 15u) {
            unsigned rr = atomicAdd(&g_root, 1u);
            if ((rr & 15u) == 15u) atomicAdd(&g_epoch, 1u);
        }
        while (*((volatile unsigned*)&g_epoch) < target) __nanosleep(32);
        __threadfence();
    }
    __syncthreads();
}

// NB = number of active 8-node blocks (1..4)
template<int NB>
static __device__ __forceinline__ void tile_compute(
    const uint4* __restrict__ ai,
    unsigned bh_base, unsigned bl_base,
    unsigned lm_off_p0, unsigned lm_off_p1,
    float acc[4][4])
{
    #pragma unroll 4
    for (int kk = 0; kk < 16; kk++) {
        uint4 ah = __ldg(ai);
        uint4 al = __ldg(ai + 1);
        ai += 64;
        unsigned kb = (unsigned)kk * 32;

        unsigned bh0, bh1, bh2, bh3, bl0, bl1, bl2, bl3;
        ldmat4(bh0, bh1, bh2, bh3, bh_base + lm_off_p0 + kb);
        ldmat4(bl0, bl1, bl2, bl3, bl_base + lm_off_p0 + kb);
        mma16816(acc[0], ah, bh0, bh1);
        mma16816(acc[0], ah, bl0, bl1);
        mma16816(acc[0], al, bh0, bh1);
        mma16816(acc[0], al, bl0, bl1);
        if (NB > 1) {
            mma16816(acc[1], ah, bh2, bh3);
            mma16816(acc[1], ah, bl2, bl3);
            mma16816(acc[1], al, bh2, bh3);
            mma16816(acc[1], al, bl2, bl3);
        }
        if (NB > 2) {
            unsigned ch0, ch1, ch2, ch3, cl0, cl1, cl2, cl3;
            ldmat4(ch0, ch1, ch2, ch3, bh_base + lm_off_p1 + kb);
            ldmat4(cl0, cl1, cl2, cl3, bl_base + lm_off_p1 + kb);
            mma16816(acc[2], ah, ch0, ch1);
            mma16816(acc[2], ah, cl0, cl1);
            mma16816(acc[2], al, ch0, ch1);
            mma16816(acc[2], al, cl0, cl1);
            if (NB > 3) {
                mma16816(acc[3], ah, ch2, ch3);
                mma16816(acc[3], ah, cl2, cl3);
                mma16816(acc[3], al, ch2, ch3);
                mma16816(acc[3], al, cl2, cl3);
            }
        }
    }
}

// ---------------------------------------------------------------------------
// K3: persistent levels kernel, HMMA split-bf16, static tile worklist
// ---------------------------------------------------------------------------
__global__ void __launch_bounds__(256, 2)
levels_kernel(const float* __restrict__ rule_b)
{
    __shared__ __align__(16) unsigned char Bh[TILE_N * BPITCH_B];
    __shared__ __align__(16) unsigned char Bl[TILE_N * BPITCH_B];
    __shared__ int s_meta[96];

    int tid  = threadIdx.x;
    int wid  = tid >> 5;
    int lane = tid & 31;

    unsigned bh_base = (unsigned)__cvta_generic_to_shared(Bh);
    unsigned bl_base = (unsigned)__cvta_generic_to_shared(Bl);

    int g    = lane >> 3;
    int row8 = lane & 7;
    unsigned lm_koff   = (unsigned)(g & 1) * 16;
    unsigned lm_off_p0 = (unsigned)((0 * 2 + (g >> 1)) * 8 + row8) * BPITCH_B + lm_koff;
    unsigned lm_off_p1 = (unsigned)((1 * 2 + (g >> 1)) * 8 + row8) * BPITCH_B + lm_koff;

    for (int lvl = 0; lvl < LVLS; lvl++) {
        int ntl = g_ntiles[lvl];
        for (int t = blockIdx.x; t < ntl; t += NCTA) {
            unsigned dsc = g_tiledesc[lvl * MAXT + t];
            int r    = (int)(dsc >> 18);
            int base = (int)((dsc >> 6) & 0xFFFu);
            int nact = (int)(dsc & 63u);

            if (tid < TILE_N) {
                int4 pk = (tid < nact) ? g_pack[lvl * M + base + tid]
                                       : make_int4(-1, 0, 0, 0);
                s_meta[tid] = pk.x; s_meta[32 + tid] = pk.y; s_meta[64 + tid] = pk.z;
            }
            __syncthreads();

            // PE gather + split-bf16 into Bh/Bl ([n][k] row-major, pitch 528B)
            {
                int s   = tid >> 3;        // node 0..31
                int seg = tid & 7;         // 32-k segment
                int j = s_meta[s];
                if (j >= 0) {
                    int p    = (seg < 4) ? s_meta[32 + s] : s_meta[64 + s];
                    int poff = (seg & 3) * 32;
                    const float4* src = (const float4*)(g_store + (size_t)p * D + poff);
                    unsigned char* dh = Bh + s * BPITCH_B + seg * 64;
                    unsigned char* dl = Bl + s * BPITCH_B + seg * 64;
                    #pragma unroll
                    for (int q = 0; q < 8; q += 2) {
                        float4 f0 = __ldcg(src + q);
                        float4 f1 = __ldcg(src + q + 1);
                        float h0x = bf16_hi_part(f0.x), h0y = bf16_hi_part(f0.y);
                        float h0z = bf16_hi_part(f0.z), h0w = bf16_hi_part(f0.w);
                        float h1x = bf16_hi_part(f1.x), h1y = bf16_hi_part(f1.y);
                        float h1z = bf16_hi_part(f1.z), h1w = bf16_hi_part(f1.w);
                        *(uint2*)(dh + q * 8) =
                            make_uint2(pack_bf16x2(h0x, h0y), pack_bf16x2(h0z, h0w));
                        *(uint2*)(dh + q * 8 + 8) =
                            make_uint2(pack_bf16x2(h1x, h1y), pack_bf16x2(h1z, h1w));
                        *(uint2*)(dl + q * 8) =
                            make_uint2(pack_bf16x2(f0.x - h0x, f0.y - h0y),
                                       pack_bf16x2(f0.z - h0z, f0.w - h0w));
                        *(uint2*)(dl + q * 8 + 8) =
                            make_uint2(pack_bf16x2(f1.x - h1x, f1.y - h1y),
                                       pack_bf16x2(f1.z - h1z, f1.w - h1w));
                    }
                }
            }
            __syncthreads();

            // compute: warp wid -> output rows 16*wid..+15; skip dead n-blocks
            {
                float acc[4][4];
                #pragma unroll
                for (int nb = 0; nb < 4; nb++)
                    #pragma unroll
                    for (int q = 0; q < 4; q++) acc[nb][q] = 0.0f;

                const uint4* ai = (const uint4*)(g_Wimg + (size_t)r * WIMG_BYTES)
                                  + (size_t)(wid * 512 + lane) * 2;

                int nblk = (nact + 7) >> 3;
                switch (nblk) {
                    case 4: tile_compute<4>(ai, bh_base, bl_base, lm_off_p0, lm_off_p1, acc); break;
                    case 3: tile_compute<3>(ai, bh_base, bl_base, lm_off_p0, lm_off_p1, acc); break;
                    case 2: tile_compute<2>(ai, bh_base, bl_base, lm_off_p0, lm_off_p1, acc); break;
                    default: tile_compute<1>(ai, bh_base, bl_base, lm_off_p0, lm_off_p1, acc); break;
                }

                int m_lo = wid * 16 + (lane >> 2);
                int m_hi = m_lo + 8;
                float bias_lo = __ldg(rule_b + r * 128 + m_lo);
                float bias_hi = __ldg(rule_b + r * 128 + m_hi);
                size_t lvlbase = (size_t)N_INIT + (size_t)lvl * M;

                #pragma unroll
                for (int nb = 0; nb < 4; nb++) {
                    if (nb < nblk) {
                        int n0 = nb * 8 + (lane & 3) * 2;
                        int j0 = s_meta[n0], j1 = s_meta[n0 + 1];
                        if (j0 >= 0) {
                            g_store[(lvlbase + j0) * D + m_lo] = fmaxf(acc[nb][0] + bias_lo, 0.f);
                            g_store[(lvlbase + j0) * D + m_hi] = fmaxf(acc[nb][2] + bias_hi, 0.f);
                        }
                        if (j1 >= 0) {
                            g_store[(lvlbase + j1) * D + m_lo] = fmaxf(acc[nb][1] + bias_lo, 0.f);
                            g_store[(lvlbase + j1) * D + m_hi] = fmaxf(acc[nb][3] + bias_hi, 0.f);
                        }
                    }
                }
            }
            __syncthreads();   // done with Bh/Bl/meta before next tile
        }
        if (lvl != LVLS - 1) grid_barrier((unsigned)(lvl + 1));
    }
}

// ---------------------------------------------------------------------------
// K4: eval + partial reductions
// ---------------------------------------------------------------------------
__global__ void eval_kernel(const float* __restrict__ eval_w,
                            const float* __restrict__ eval_b,
                            const float* __restrict__ pos_vals,
                            const float* __restrict__ neg_vals)
{
    __shared__ float4 sw[32];
    __shared__ float  wacc[8][6];
    if (threadIdx.x < 32) sw[threadIdx.x] = ((const float4*)eval_w)[threadIdx.x];
    __syncthreads();

    int wid  = threadIdx.x >> 5;
    int lane = threadIdx.x & 31;
    int gw     = blockIdx.x * 8 + wid;
    int nwarps = EVAL_BLOCKS * 8;
    float eb = eval_b[0];
    float4 w4 = sw[lane];

    float A = 0.f, B = 0.f, pok = 0.f, nok = 0.f, spv = 0.f, snv = 0.f;

    for (size_t node = gw; node < (size_t)N_TOT; node += nwarps) {
        float4 v = ((const float4*)(g_store + node * D))[lane];
        float d = v.x * w4.x + v.y * w4.y + v.z * w4.z + v.w * w4.w;
        #pragma unroll
        for (int off = 16; off; off >>= 1) d += __shfl_down_sync(0xffffffffu, d, off);
        if (lane == 0) {
            float l  = d + eb;
            float pv = pos_vals[node], nv = neg_vals[node];
            float spn = log1pf(expf(-fabsf(l)));
            float sp_pos = spn + fmaxf(l, 0.f);
            float sp_neg = spn + fmaxf(-l, 0.f);
            A += pv * sp_neg;
            B += nv * sp_pos;
            if (l >= 0.f) pok += pv; else nok += nv;
            spv += pv;
            snv += nv;
        }
    }

    if (lane == 0) {
        wacc[wid][0] = A;   wacc[wid][1] = B;
        wacc[wid][2] = pok; wacc[wid][3] = nok;
        wacc[wid][4] = spv; wacc[wid][5] = snv;
    }
    __syncthreads();
    if (threadIdx.x == 0) {
        float o[6] = {0, 0, 0, 0, 0, 0};
        for (int w = 0; w < 8; w++)
            for (int k = 0; k < 6; k++) o[k] += wacc[w][k];
        for (int k = 0; k < 6; k++) g_partial[blockIdx.x * 6 + k] = o[k];
    }
}

__global__ void final_kernel(float* __restrict__ out)
{
    if (blockIdx.x == 0 && threadIdx.x == 0) {
        float A = 0.f, B = 0.f, pok = 0.f, nok = 0.f, spv = 0.f, snv = 0.f;
        for (int b = 0; b < EVAL_BLOCKS; b++) {
            A   += g_partial[b * 6 + 0];
            B   += g_partial[b * 6 + 1];
            pok += g_partial[b * 6 + 2];
            nok += g_partial[b * 6 + 3];
            spv += g_partial[b * 6 + 4];
            snv += g_partial[b * 6 + 5];
        }
        float pw = snv / spv;
        out[0] = pw * A + B;
        out[1] = pok;
        out[2] = nok;
    }
}

// ---------------------------------------------------------------------------
extern "C" void kernel_launch(void* const* d_in, const int* in_sizes, int n_in,
                              void* d_out, int out_size)
{
    const float* thax_table = (const float*)d_in[0];
    const float* sine_table = (const float*)d_in[1];
    const float* rule_W     = (const float*)d_in[2];
    const float* rule_b     = (const float*)d_in[3];
    const float* eval_w     = (const float*)d_in[4];
    const float* eval_b     = (const float*)d_in[5];
    const float* pos_vals   = (const float*)d_in[6];
    const float* neg_vals   = (const float*)d_in[7];
    const int*   init_thax  = (const int*)d_in[8];
    const int*   init_sine  = (const int*)d_in[9];
    const int*   parents    = (const int*)d_in[10];
    const int*   rules      = (const int*)d_in[11];

    (void)in_sizes; (void)n_in; (void)out_size;

    cudaFuncSetAttribute(convw_kernel,
                         cudaFuncAttributeMaxDynamicSharedMemorySize, 131072);

    init_embed_kernel<<<2048, 256>>>((const float4*)thax_table,
                                     (const float4*)sine_table,
                                     init_thax, init_sine);
    convw_kernel<<<N_RULES, 256, 131072>>>(rule_W);
    group_kernel<<<LVLS, 256>>>(rules, parents);
    levels_kernel<<<NCTA, 256>>>(rule_b);
    eval_kernel<<<EVAL_BLOCKS, 256>>>(eval_w, eval_b, pos_vals, neg_vals);
    final_kernel<<<1, 32>>>((float*)d_out);
}

// round 7
// speedup vs baseline: 4.0270x; 1.1290x over previous
#include <cuda_runtime.h>
#include <cuda_bf16.h>
#include <cstdint>

#define D        128
#define N_INIT   100000
#define LVLS     64
#define M        4096
#define N_RULES  256
#define N_TOT    (N_INIT + LVLS * M)

#define NCTA     256           // persistent CTAs = rules, 2 per SM, single wave
#define TILE_N   32
#define EVAL_BLOCKS 1024

// B smem pitch: 264 bf16 = 528 bytes (132 words -> bank shift 4/row, conflict-free)
#define BPITCH_B 528
// per-rule hi/lo fragment image: 8 warps x 16 ksteps x 32 lanes x 16B
#define WIMG_BYTES 65536

__device__ float g_store[(size_t)N_TOT * D];
__device__ int   g_order[LVLS * M];
__device__ int   g_ruleoff[LVLS * (N_RULES + 1)];
__device__ int4  g_pack[LVLS * M];               // (j, p0, p1, 0) per grouped slot
__device__ float g_partial[EVAL_BLOCKS * 6];
__device__ unsigned g_grp[16];
__device__ unsigned g_root;
__device__ unsigned g_epoch;
__device__ unsigned char g_WimgHi[(size_t)N_RULES * WIMG_BYTES];
__device__ unsigned char g_WimgLo[(size_t)N_RULES * WIMG_BYTES];

static __device__ __forceinline__ unsigned pack_bf16x2(float lo, float hi) {
    unsigned short a = __bfloat16_as_ushort(__float2bfloat16_rn(lo));
    unsigned short b = __bfloat16_as_ushort(__float2bfloat16_rn(hi));
    return (unsigned)a | ((unsigned)b << 16);
}
static __device__ __forceinline__ float bf16_hi_part(float v) {
    return __bfloat162float(__float2bfloat16_rn(v));
}

// ---------------------------------------------------------------------------
// K1: init embeddings
// ---------------------------------------------------------------------------
__global__ void init_embed_kernel(const float4* __restrict__ thax,
                                  const float4* __restrict__ sine,
                                  const int* __restrict__ it,
                                  const int* __restrict__ is)
{
    int tid = blockIdx.x * blockDim.x + threadIdx.x;
    int total = N_INIT * (D / 4);
    float4* st = (float4*)g_store;
    for (int k = tid; k < total; k += gridDim.x * blockDim.x) {
        int i = k >> 5;
        int c = k & 31;
        float4 a = thax[(size_t)it[i] * 32 + c];
        float4 b = sine[(size_t)is[i] * 32 + c];
        st[(size_t)i * 32 + c] = make_float4(a.x + b.x, a.y + b.y, a.z + b.z, a.w + b.w);
    }
}

// ---------------------------------------------------------------------------
// K1b: convert rule_W -> fragment-ordered bf16 hi/lo images (separate planes).
// A[m][k] = rule_W[r][k][m]. Entry (w,kk,lane): 16B = {a0,a1,a2,a3} bf16x2
//   m0 = 16w + lane/4, k0 = 16kk + (lane%4)*2
// ---------------------------------------------------------------------------
__global__ void convw_kernel(const float* __restrict__ rule_W)
{
    extern __shared__ float Wsm[];            // [256][128]
    int r   = blockIdx.x;
    int tid = threadIdx.x;

    const float4* src = (const float4*)(rule_W + (size_t)r * 32768);
    #pragma unroll 4
    for (int i = tid; i < 8192; i += 256) ((float4*)Wsm)[i] = __ldg(src + i);
    __syncthreads();

    unsigned char* dh = g_WimgHi + (size_t)r * WIMG_BYTES;
    unsigned char* dl = g_WimgLo + (size_t)r * WIMG_BYTES;
    for (int idx = tid; idx < 4096; idx += 256) {
        int lane = idx & 31, kk = (idx >> 5) & 15, w = idx >> 9;
        int m0 = w * 16 + (lane >> 2);
        int k0 = kk * 16 + (lane & 3) * 2;

        float v[8];
        v[0] = Wsm[(k0)     * 128 + m0];     v[1] = Wsm[(k0 + 1) * 128 + m0];
        v[2] = Wsm[(k0)     * 128 + m0 + 8]; v[3] = Wsm[(k0 + 1) * 128 + m0 + 8];
        v[4] = Wsm[(k0 + 8) * 128 + m0];     v[5] = Wsm[(k0 + 9) * 128 + m0];
        v[6] = Wsm[(k0 + 8) * 128 + m0 + 8]; v[7] = Wsm[(k0 + 9) * 128 + m0 + 8];

        unsigned h[4], l[4];
        #pragma unroll
        for (int j = 0; j < 4; j++) {
            float h0 = bf16_hi_part(v[2*j]),   h1 = bf16_hi_part(v[2*j+1]);
            h[j] = pack_bf16x2(h0, h1);
            l[j] = pack_bf16x2(v[2*j] - h0, v[2*j+1] - h1);
        }
        *(uint4*)(dh + (size_t)idx * 16) = make_uint4(h[0], h[1], h[2], h[3]);
        *(uint4*)(dl + (size_t)idx * 16) = make_uint4(l[0], l[1], l[2], l[3]);
    }
}

// ---------------------------------------------------------------------------
// K2: group by rule + pack (j,p0,p1) + offsets + reset barrier
// ---------------------------------------------------------------------------
__global__ void group_kernel(const int* __restrict__ rules,
                             const int* __restrict__ parents)
{
    int lvl = blockIdx.x;
    int tid = threadIdx.x;
    __shared__ int counts[N_RULES];
    __shared__ int offs[N_RULES + 1];
    __shared__ int cursor[N_RULES];

    if (lvl == 0) {           // reset tree-barrier state each replay
        if (tid < 16) g_grp[tid] = 0;
        if (tid == 16) g_root = 0;
        if (tid == 17) g_epoch = 0;
    }

    for (int r = tid; r < N_RULES; r += blockDim.x) counts[r] = 0;
    __syncthreads();
    for (int j = tid; j < M; j += blockDim.x)
        atomicAdd(&counts[rules[lvl * M + j]], 1);
    __syncthreads();
    if (tid == 0) {
        int s = 0;
        for (int r = 0; r < N_RULES; r++) { offs[r] = s; s += counts[r]; }
        offs[N_RULES] = s;
    }
    __syncthreads();
    for (int r = tid; r < N_RULES; r += blockDim.x) cursor[r] = offs[r];
    for (int r = tid; r <= N_RULES; r += blockDim.x)
        g_ruleoff[lvl * (N_RULES + 1) + r] = offs[r];
    __syncthreads();
    for (int j = tid; j < M; j += blockDim.x) {
        int r = rules[lvl * M + j];
        int p = atomicAdd(&cursor[r], 1);
        g_order[lvl * M + p] = j;
    }
    __syncthreads();

    // pack (j, p0, p1) per slot
    for (int slot = tid; slot < M; slot += blockDim.x) {
        int j = g_order[lvl * M + slot];
        int4 pk;
        pk.x = j;
        pk.y = parents[((size_t)lvl * M + j) * 2 + 0];
        pk.z = parents[((size_t)lvl * M + j) * 2 + 1];
        pk.w = 0;
        g_pack[lvl * M + slot] = pk;
    }
}

// ---------------------------------------------------------------------------
// mma helpers
// ---------------------------------------------------------------------------
static __device__ __forceinline__ void mma16816(float* c, const uint4& a,
                                                unsigned b0, unsigned b1)
{
    asm volatile(
        "mma.sync.aligned.m16n8k16.row.col.f32.bf16.bf16.f32 "
        "{%0,%1,%2,%3}, {%4,%5,%6,%7}, {%8,%9}, {%0,%1,%2,%3};"
        : "+f"(c[0]), "+f"(c[1]), "+f"(c[2]), "+f"(c[3])
        : "r"(a.x), "r"(a.y), "r"(a.z), "r"(a.w), "r"(b0), "r"(b1));
}
static __device__ __forceinline__ void ldmat4(unsigned& r0, unsigned& r1,
                                              unsigned& r2, unsigned& r3, unsigned addr)
{
    asm volatile("ldmatrix.sync.aligned.m8n8.x4.shared.b16 {%0,%1,%2,%3}, [%4];"
                 : "=r"(r0), "=r"(r1), "=r"(r2), "=r"(r3) : "r"(addr));
}
static __device__ __forceinline__ uint4 ldg_cg16(const uint4* p)
{
    uint4 v;
    asm volatile("ld.global.cg.v4.u32 {%0,%1,%2,%3}, [%4];"
                 : "=r"(v.x), "=r"(v.y), "=r"(v.z), "=r"(v.w) : "l"(p));
    return v;
}

// two-level tree barrier: 16 groups x 16 CTAs, monotonic counters
__device__ __forceinline__ void grid_barrier(unsigned target)
{
    __syncthreads();
    if (threadIdx.x == 0) {
        __threadfence();
        unsigned g = blockIdx.x >> 4;
        unsigned v = atomicAdd(&g_grp[g], 1u);
        if ((v & 15u) == 15u) {
            unsigned rr = atomicAdd(&g_root, 1u);
            if ((rr & 15u) == 15u) atomicAdd(&g_epoch, 1u);
        }
        while (*((volatile unsigned*)&g_epoch) < target) __nanosleep(32);
        __threadfence();
    }
    __syncthreads();
}

// NB = number of active 8-node blocks (1..4); 3-term split-bf16
template<int NB>
static __device__ __forceinline__ void tile_compute(
    const uint4* __restrict__ ahp,      // hi image (L1-resident, pinned rule)
    const uint4* __restrict__ alp,      // lo image (streamed, .cg)
    unsigned bh_base, unsigned bl_base,
    unsigned lm_off_p0, unsigned lm_off_p1,
    float acc[4][4])
{
    #pragma unroll 4
    for (int kk = 0; kk < 16; kk++) {
        uint4 ah = __ldg(ahp);          // L1 hit after first tile of this rule
        uint4 al = ldg_cg16(alp);       // L2 stream
        ahp += 32; alp += 32;
        unsigned kb = (unsigned)kk * 32;

        unsigned bh0, bh1, bh2, bh3, bl0, bl1, bl2, bl3;
        ldmat4(bh0, bh1, bh2, bh3, bh_base + lm_off_p0 + kb);
        ldmat4(bl0, bl1, bl2, bl3, bl_base + lm_off_p0 + kb);
        mma16816(acc[0], ah, bh0, bh1);
        mma16816(acc[0], ah, bl0, bl1);
        mma16816(acc[0], al, bh0, bh1);
        if (NB > 1) {
            mma16816(acc[1], ah, bh2, bh3);
            mma16816(acc[1], ah, bl2, bl3);
            mma16816(acc[1], al, bh2, bh3);
        }
        if (NB > 2) {
            unsigned ch0, ch1, ch2, ch3, cl0, cl1, cl2, cl3;
            ldmat4(ch0, ch1, ch2, ch3, bh_base + lm_off_p1 + kb);
            ldmat4(cl0, cl1, cl2, cl3, bl_base + lm_off_p1 + kb);
            mma16816(acc[2], ah, ch0, ch1);
            mma16816(acc[2], ah, cl0, cl1);
            mma16816(acc[2], al, ch0, ch1);
            if (NB > 3) {
                mma16816(acc[3], ah, ch2, ch3);
                mma16816(acc[3], ah, cl2, cl3);
                mma16816(acc[3], al, ch2, ch3);
            }
        }
    }
}

// ---------------------------------------------------------------------------
// K3: persistent levels kernel, rule pinned to CTA, hi-plane L1-resident
// ---------------------------------------------------------------------------
__global__ void __launch_bounds__(256, 2)
levels_kernel(const float* __restrict__ rule_b)
{
    __shared__ __align__(16) unsigned char Bh[TILE_N * BPITCH_B];
    __shared__ __align__(16) unsigned char Bl[TILE_N * BPITCH_B];
    __shared__ int s_meta[96];

    int tid  = threadIdx.x;
    int wid  = tid >> 5;
    int lane = tid & 31;
    int r    = blockIdx.x;           // pinned rule

    unsigned bh_base = (unsigned)__cvta_generic_to_shared(Bh);
    unsigned bl_base = (unsigned)__cvta_generic_to_shared(Bl);

    int g    = lane >> 3;
    int row8 = lane & 7;
    unsigned lm_koff   = (unsigned)(g & 1) * 16;
    unsigned lm_off_p0 = (unsigned)((0 * 2 + (g >> 1)) * 8 + row8) * BPITCH_B + lm_koff;
    unsigned lm_off_p1 = (unsigned)((1 * 2 + (g >> 1)) * 8 + row8) * BPITCH_B + lm_koff;

    const uint4* ahi0 = (const uint4*)(g_WimgHi + (size_t)r * WIMG_BYTES)
                        + (size_t)wid * 512 + lane;
    const uint4* alo0 = (const uint4*)(g_WimgLo + (size_t)r * WIMG_BYTES)
                        + (size_t)wid * 512 + lane;

    int m_lo = wid * 16 + (lane >> 2);
    int m_hi = m_lo + 8;
    float bias_lo = __ldg(rule_b + r * 128 + m_lo);
    float bias_hi = __ldg(rule_b + r * 128 + m_hi);

    for (int lvl = 0; lvl < LVLS; lvl++) {
        int start = g_ruleoff[lvl * (N_RULES + 1) + r];
        int end   = g_ruleoff[lvl * (N_RULES + 1) + r + 1];

        for (int tb = start; tb < end; tb += TILE_N) {
            int nact = min(TILE_N, end - tb);

            if (tid < TILE_N) {
                int4 pk = (tid < nact) ? g_pack[lvl * M + tb + tid]
                                       : make_int4(-1, 0, 0, 0);
                s_meta[tid] = pk.x; s_meta[32 + tid] = pk.y; s_meta[64 + tid] = pk.z;
            }
            __syncthreads();

            // PE gather + split-bf16 into Bh/Bl ([n][k] row-major, pitch 528B)
            {
                int s   = tid >> 3;        // node 0..31
                int seg = tid & 7;         // 32-k segment
                int j = s_meta[s];
                if (j >= 0) {
                    int p    = (seg < 4) ? s_meta[32 + s] : s_meta[64 + s];
                    int poff = (seg & 3) * 32;
                    const float4* src = (const float4*)(g_store + (size_t)p * D + poff);
                    unsigned char* dh = Bh + s * BPITCH_B + seg * 64;
                    unsigned char* dl = Bl + s * BPITCH_B + seg * 64;
                    #pragma unroll
                    for (int q = 0; q < 8; q += 2) {
                        float4 f0 = __ldcg(src + q);
                        float4 f1 = __ldcg(src + q + 1);
                        float h0x = bf16_hi_part(f0.x), h0y = bf16_hi_part(f0.y);
                        float h0z = bf16_hi_part(f0.z), h0w = bf16_hi_part(f0.w);
                        float h1x = bf16_hi_part(f1.x), h1y = bf16_hi_part(f1.y);
                        float h1z = bf16_hi_part(f1.z), h1w = bf16_hi_part(f1.w);
                        *(uint2*)(dh + q * 8) =
                            make_uint2(pack_bf16x2(h0x, h0y), pack_bf16x2(h0z, h0w));
                        *(uint2*)(dh + q * 8 + 8) =
                            make_uint2(pack_bf16x2(h1x, h1y), pack_bf16x2(h1z, h1w));
                        *(uint2*)(dl + q * 8) =
                            make_uint2(pack_bf16x2(f0.x - h0x, f0.y - h0y),
                                       pack_bf16x2(f0.z - h0z, f0.w - h0w));
                        *(uint2*)(dl + q * 8 + 8) =
                            make_uint2(pack_bf16x2(f1.x - h1x, f1.y - h1y),
                                       pack_bf16x2(f1.z - h1z, f1.w - h1w));
                    }
                }
            }
            __syncthreads();

            // compute: warp wid -> output rows 16*wid..+15; skip dead n-blocks
            {
                float acc[4][4];
                #pragma unroll
                for (int nb = 0; nb < 4; nb++)
                    #pragma unroll
                    for (int q = 0; q < 4; q++) acc[nb][q] = 0.0f;

                int nblk = (nact + 7) >> 3;
                switch (nblk) {
                    case 4: tile_compute<4>(ahi0, alo0, bh_base, bl_base, lm_off_p0, lm_off_p1, acc); break;
                    case 3: tile_compute<3>(ahi0, alo0, bh_base, bl_base, lm_off_p0, lm_off_p1, acc); break;
                    case 2: tile_compute<2>(ahi0, alo0, bh_base, bl_base, lm_off_p0, lm_off_p1, acc); break;
                    default: tile_compute<1>(ahi0, alo0, bh_base, bl_base, lm_off_p0, lm_off_p1, acc); break;
                }

                size_t lvlbase = (size_t)N_INIT + (size_t)lvl * M;
                #pragma unroll
                for (int nb = 0; nb < 4; nb++) {
                    if (nb < nblk) {
                        int n0 = nb * 8 + (lane & 3) * 2;
                        int j0 = s_meta[n0], j1 = s_meta[n0 + 1];
                        if (j0 >= 0) {
                            g_store[(lvlbase + j0) * D + m_lo] = fmaxf(acc[nb][0] + bias_lo, 0.f);
                            g_store[(lvlbase + j0) * D + m_hi] = fmaxf(acc[nb][2] + bias_hi, 0.f);
                        }
                        if (j1 >= 0) {
                            g_store[(lvlbase + j1) * D + m_lo] = fmaxf(acc[nb][1] + bias_lo, 0.f);
                            g_store[(lvlbase + j1) * D + m_hi] = fmaxf(acc[nb][3] + bias_hi, 0.f);
                        }
                    }
                }
            }
            __syncthreads();   // done with Bh/Bl/meta before next tile
        }
        if (lvl != LVLS - 1) grid_barrier((unsigned)(lvl + 1));
    }
}

// ---------------------------------------------------------------------------
// K4: eval + partial reductions
// ---------------------------------------------------------------------------
__global__ void eval_kernel(const float* __restrict__ eval_w,
                            const float* __restrict__ eval_b,
                            const float* __restrict__ pos_vals,
                            const float* __restrict__ neg_vals)
{
    __shared__ float4 sw[32];
    __shared__ float  wacc[8][6];
    if (threadIdx.x < 32) sw[threadIdx.x] = ((const float4*)eval_w)[threadIdx.x];
    __syncthreads();

    int wid  = threadIdx.x >> 5;
    int lane = threadIdx.x & 31;
    int gw     = blockIdx.x * 8 + wid;
    int nwarps = EVAL_BLOCKS * 8;
    float eb = eval_b[0];
    float4 w4 = sw[lane];

    float A = 0.f, B = 0.f, pok = 0.f, nok = 0.f, spv = 0.f, snv = 0.f;

    for (size_t node = gw; node < (size_t)N_TOT; node += nwarps) {
        float4 v = ((const float4*)(g_store + node * D))[lane];
        float d = v.x * w4.x + v.y * w4.y + v.z * w4.z + v.w * w4.w;
        #pragma unroll
        for (int off = 16; off; off >>= 1) d += __shfl_down_sync(0xffffffffu, d, off);
        if (lane == 0) {
            float l  = d + eb;
            float pv = pos_vals[node], nv = neg_vals[node];
            float spn = log1pf(expf(-fabsf(l)));
            float sp_pos = spn + fmaxf(l, 0.f);
            float sp_neg = spn + fmaxf(-l, 0.f);
            A += pv * sp_neg;
            B += nv * sp_pos;
            if (l >= 0.f) pok += pv; else nok += nv;
            spv += pv;
            snv += nv;
        }
    }

    if (lane == 0) {
        wacc[wid][0] = A;   wacc[wid][1] = B;
        wacc[wid][2] = pok; wacc[wid][3] = nok;
        wacc[wid][4] = spv; wacc[wid][5] = snv;
    }
    __syncthreads();
    if (threadIdx.x == 0) {
        float o[6] = {0, 0, 0, 0, 0, 0};
        for (int w = 0; w < 8; w++)
            for (int k = 0; k < 6; k++) o[k] += wacc[w][k];
        for (int k = 0; k < 6; k++) g_partial[blockIdx.x * 6 + k] = o[k];
    }
}

__global__ void final_kernel(float* __restrict__ out)
{
    if (blockIdx.x == 0 && threadIdx.x == 0) {
        float A = 0.f, B = 0.f, pok = 0.f, nok = 0.f, spv = 0.f, snv = 0.f;
        for (int b = 0; b < EVAL_BLOCKS; b++) {
            A   += g_partial[b * 6 + 0];
            B   += g_partial[b * 6 + 1];
            pok += g_partial[b * 6 + 2];
            nok += g_partial[b * 6 + 3];
            spv += g_partial[b * 6 + 4];
            snv += g_partial[b * 6 + 5];
        }
        float pw = snv / spv;
        out[0] = pw * A + B;
        out[1] = pok;
        out[2] = nok;
    }
}

// ---------------------------------------------------------------------------
extern "C" void kernel_launch(void* const* d_in, const int* in_sizes, int n_in,
                              void* d_out, int out_size)
{
    const float* thax_table = (const float*)d_in[0];
    const float* sine_table = (const float*)d_in[1];
    const float* rule_W     = (const float*)d_in[2];
    const float* rule_b     = (const float*)d_in[3];
    const float* eval_w     = (const float*)d_in[4];
    const float* eval_b     = (const float*)d_in[5];
    const float* pos_vals   = (const float*)d_in[6];
    const float* neg_vals   = (const float*)d_in[7];
    const int*   init_thax  = (const int*)d_in[8];
    const int*   init_sine  = (const int*)d_in[9];
    const int*   parents    = (const int*)d_in[10];
    const int*   rules      = (const int*)d_in[11];

    (void)in_sizes; (void)n_in; (void)out_size;

    cudaFuncSetAttribute(convw_kernel,
                         cudaFuncAttributeMaxDynamicSharedMemorySize, 131072);

    init_embed_kernel<<<2048, 256>>>((const float4*)thax_table,
                                     (const float4*)sine_table,
                                     init_thax, init_sine);
    convw_kernel<<<N_RULES, 256, 131072>>>(rule_W);
    group_kernel<<<LVLS, 256>>>(rules, parents);
    levels_kernel<<<NCTA, 256>>>(rule_b);
    eval_kernel<<<EVAL_BLOCKS, 256>>>(eval_w, eval_b, pos_vals, neg_vals);
    final_kernel<<<1, 32>>>((float*)d_out);
}